// round 1
// baseline (speedup 1.0000x reference)
#include <cuda_runtime.h>
#include <cuda_bf16.h>
#include <math.h>

// Problem constants
#define Bb 4
#define Tt 512
#define Cc 1024
#define Hh 16
#define Ll 8
#define FSs 64
#define Vv 3
#define Dd 64          // head dim
#define Mrows (Bb*Tt)  // 2048

// ---------------------------------------------------------------------------
// Device-global scratch (no allocations allowed)
// ---------------------------------------------------------------------------
__device__ float g_x  [Mrows * Cc];        // residual stream
__device__ float g_h  [Mrows * Cc];        // LN output / final LN
__device__ float g_qkv[Mrows * 3 * Cc];    // qkv
__device__ float g_y  [Mrows * Cc];        // attention output
__device__ float g_fc [Mrows * 4 * Cc];    // MLP hidden

// ---------------------------------------------------------------------------
// Embedding: x[m,c] = sum_f seqs[m,f]*wte_w[f,c] + wte_b[c] + wpe[t,c]
// grid = Mrows, block = 256; each thread does 4 columns.
// ---------------------------------------------------------------------------
__global__ void embed_kernel(const float* __restrict__ seqs,
                             const float* __restrict__ wte_w,
                             const float* __restrict__ wte_b,
                             const float* __restrict__ wpe,
                             float* __restrict__ x)
{
    int m = blockIdx.x;
    int t = m % Tt;
    __shared__ float sf[FSs];
    if (threadIdx.x < FSs) sf[threadIdx.x] = seqs[m * FSs + threadIdx.x];
    __syncthreads();

    #pragma unroll
    for (int cc = 0; cc < 4; cc++) {
        int c = threadIdx.x + cc * 256;
        float acc = wte_b[c] + wpe[t * Cc + c];
        #pragma unroll 8
        for (int f = 0; f < FSs; f++)
            acc = fmaf(sf[f], wte_w[f * Cc + c], acc);
        x[m * Cc + c] = acc;
    }
}

// ---------------------------------------------------------------------------
// LayerNorm: one block per row (C=1024), 256 threads, 4 elems/thread.
// ---------------------------------------------------------------------------
__global__ void ln_kernel(const float* __restrict__ x,
                          const float* __restrict__ s,
                          const float* __restrict__ b,
                          float* __restrict__ out)
{
    int row = blockIdx.x;
    int tid = threadIdx.x;
    const float* xr = x + (size_t)row * Cc;

    float v[4];
    float sum = 0.f, sumsq = 0.f;
    #pragma unroll
    for (int i = 0; i < 4; i++) {
        v[i] = xr[tid + i * 256];
        sum += v[i];
        sumsq += v[i] * v[i];
    }

    __shared__ float red1[256], red2[256];
    red1[tid] = sum; red2[tid] = sumsq;
    __syncthreads();
    for (int off = 128; off > 0; off >>= 1) {
        if (tid < off) { red1[tid] += red1[tid + off]; red2[tid] += red2[tid + off]; }
        __syncthreads();
    }
    float mean = red1[0] * (1.0f / Cc);
    float var  = red2[0] * (1.0f / Cc) - mean * mean;
    float rstd = rsqrtf(var + 1e-5f);

    #pragma unroll
    for (int i = 0; i < 4; i++) {
        int c = tid + i * 256;
        out[(size_t)row * Cc + c] = (v[i] - mean) * rstd * s[c] + b[c];
    }
}

// ---------------------------------------------------------------------------
// Tiled SGEMM: C = A[M,K] @ B[K,N] + bias (+ residual) (optional ReLU).
// BM=BN=64, BK=16, 256 threads, 4x4 per thread. Dims assumed divisible.
// ---------------------------------------------------------------------------
template <bool RELU, bool RES>
__global__ void gemm_kernel(const float* __restrict__ A,
                            const float* __restrict__ Bm,
                            const float* __restrict__ bias,
                            const float* __restrict__ res,
                            float* __restrict__ C,
                            int M, int N, int K)
{
    const int BM = 64, BN = 64, BK = 16;
    __shared__ float As[BK][BM];
    __shared__ float Bs[BK][BN];

    int tid = threadIdx.x;
    int tr = tid / 16;        // 0..15
    int tc = tid % 16;        // 0..15
    int blockRow = blockIdx.y * BM;
    int blockCol = blockIdx.x * BN;

    float acc[4][4] = {};

    for (int k0 = 0; k0 < K; k0 += BK) {
        // load A tile 64x16 (transposed into As[col][row])
        #pragma unroll
        for (int e = tid; e < BM * BK; e += 256) {
            int r = e / BK, c = e % BK;
            As[c][r] = A[(size_t)(blockRow + r) * K + k0 + c];
        }
        // load B tile 16x64
        #pragma unroll
        for (int e = tid; e < BK * BN; e += 256) {
            int r = e / BN, c = e % BN;
            Bs[r][c] = Bm[(size_t)(k0 + r) * N + blockCol + c];
        }
        __syncthreads();

        #pragma unroll
        for (int kk = 0; kk < BK; kk++) {
            float a[4], bq[4];
            #pragma unroll
            for (int i = 0; i < 4; i++) a[i]  = As[kk][tr * 4 + i];
            #pragma unroll
            for (int j = 0; j < 4; j++) bq[j] = Bs[kk][tc * 4 + j];
            #pragma unroll
            for (int i = 0; i < 4; i++)
                #pragma unroll
                for (int j = 0; j < 4; j++)
                    acc[i][j] = fmaf(a[i], bq[j], acc[i][j]);
        }
        __syncthreads();
    }

    #pragma unroll
    for (int i = 0; i < 4; i++) {
        int row = blockRow + tr * 4 + i;
        #pragma unroll
        for (int j = 0; j < 4; j++) {
            int col = blockCol + tc * 4 + j;
            float vout = acc[i][j] + bias[col];
            if (RES) vout += res[(size_t)row * N + col];
            if (RELU) vout = fmaxf(vout, 0.0f);
            C[(size_t)row * N + col] = vout;
        }
    }
}

// ---------------------------------------------------------------------------
// Attention: one warp per (b, h, q) row; online softmax over valid keys.
// Each lane owns 2 of the 64 head dims (float2).
// ---------------------------------------------------------------------------
__global__ void attn_kernel(const float* __restrict__ qkv,
                            const int* __restrict__ seq_ls,
                            float* __restrict__ y)
{
    int gwarp = (blockIdx.x * blockDim.x + threadIdx.x) >> 5;
    int lane = threadIdx.x & 31;
    // gwarp -> (b, h, t)
    int t = gwarp % Tt;
    int h = (gwarp / Tt) % Hh;
    int b = gwarp / (Tt * Hh);

    const float scale = 0.125f;  // 1/sqrt(64)

    const float* qrow = qkv + ((size_t)b * Tt + t) * (3 * Cc) + h * Dd;
    float2 q = *(const float2*)(qrow + lane * 2);
    int lv = seq_ls[b];

    float mmax = -INFINITY, lsum = 0.f;
    float2 acc = make_float2(0.f, 0.f);

    const float* kbase = qkv + (size_t)b * Tt * 3 * Cc + Cc + h * Dd;
    const float* vbase = kbase + Cc;

    for (int j = 0; j < lv; j++) {
        const float* krow = kbase + (size_t)j * (3 * Cc);
        float2 kv = *(const float2*)(krow + lane * 2);
        float s = q.x * kv.x + q.y * kv.y;
        #pragma unroll
        for (int off = 16; off > 0; off >>= 1)
            s += __shfl_xor_sync(0xffffffffu, s, off);
        s *= scale;

        float mnew = fmaxf(mmax, s);
        float corr = __expf(mmax - mnew);   // 0 on first iter (m = -inf)
        float p = __expf(s - mnew);
        lsum = lsum * corr + p;

        const float* vrow = vbase + (size_t)j * (3 * Cc);
        float2 vv = *(const float2*)(vrow + lane * 2);
        acc.x = acc.x * corr + p * vv.x;
        acc.y = acc.y * corr + p * vv.y;
        mmax = mnew;
    }

    float inv = 1.0f / lsum;
    float* yrow = y + ((size_t)b * Tt + t) * Cc + h * Dd;
    yrow[lane * 2]     = acc.x * inv;
    yrow[lane * 2 + 1] = acc.y * inv;
}

// ---------------------------------------------------------------------------
// Head: logits[m, v] = sum_k xf[m,k]*hw[k,v]; V=3.
// One block of 128 threads per row.
// ---------------------------------------------------------------------------
__global__ void head_kernel(const float* __restrict__ xf,
                            const float* __restrict__ hw,
                            float* __restrict__ out)
{
    int row = blockIdx.x;
    int tid = threadIdx.x;
    float a0 = 0.f, a1 = 0.f, a2 = 0.f;
    const float* xr = xf + (size_t)row * Cc;
    for (int k = tid; k < Cc; k += 128) {
        float xv = xr[k];
        a0 = fmaf(xv, hw[k * 3 + 0], a0);
        a1 = fmaf(xv, hw[k * 3 + 1], a1);
        a2 = fmaf(xv, hw[k * 3 + 2], a2);
    }
    __shared__ float r0[128], r1[128], r2[128];
    r0[tid] = a0; r1[tid] = a1; r2[tid] = a2;
    __syncthreads();
    for (int off = 64; off > 0; off >>= 1) {
        if (tid < off) { r0[tid] += r0[tid+off]; r1[tid] += r1[tid+off]; r2[tid] += r2[tid+off]; }
        __syncthreads();
    }
    if (tid == 0) {
        out[row * 3 + 0] = r0[0];
        out[row * 3 + 1] = r1[0];
        out[row * 3 + 2] = r2[0];
    }
}

// ---------------------------------------------------------------------------
// Launch
// ---------------------------------------------------------------------------
extern "C" void kernel_launch(void* const* d_in, const int* in_sizes, int n_in,
                              void* d_out, int out_size)
{
    const float* seqs    = (const float*)d_in[0];
    const int*   seq_ls  = (const int*)  d_in[1];
    const float* wte_w   = (const float*)d_in[2];
    const float* wte_b   = (const float*)d_in[3];
    const float* wpe     = (const float*)d_in[4];
    const float* ln1_s   = (const float*)d_in[5];
    const float* ln1_b   = (const float*)d_in[6];
    const float* attn_w  = (const float*)d_in[7];
    const float* attn_b  = (const float*)d_in[8];
    const float* attnp_w = (const float*)d_in[9];
    const float* attnp_b = (const float*)d_in[10];
    const float* ln2_s   = (const float*)d_in[11];
    const float* ln2_b   = (const float*)d_in[12];
    const float* fc_w    = (const float*)d_in[13];
    const float* fc_b    = (const float*)d_in[14];
    const float* proj_w  = (const float*)d_in[15];
    const float* proj_b  = (const float*)d_in[16];
    const float* lnf_s   = (const float*)d_in[17];
    const float* lnf_b   = (const float*)d_in[18];
    const float* head_w  = (const float*)d_in[19];
    float* out = (float*)d_out;

    float *x, *h, *qkv, *y, *fc;
    cudaGetSymbolAddress((void**)&x,   g_x);
    cudaGetSymbolAddress((void**)&h,   g_h);
    cudaGetSymbolAddress((void**)&qkv, g_qkv);
    cudaGetSymbolAddress((void**)&y,   g_y);
    cudaGetSymbolAddress((void**)&fc,  g_fc);

    // Embedding
    embed_kernel<<<Mrows, 256>>>(seqs, wte_w, wte_b, wpe, x);

    for (int l = 0; l < Ll; l++) {
        // LN1
        ln_kernel<<<Mrows, 256>>>(x, ln1_s + l * Cc, ln1_b + l * Cc, h);
        // QKV GEMM [2048,1024] x [1024,3072]
        gemm_kernel<false, false><<<dim3(3 * Cc / 64, Mrows / 64), 256>>>(
            h, attn_w + (size_t)l * Cc * 3 * Cc, attn_b + (size_t)l * 3 * Cc,
            nullptr, qkv, Mrows, 3 * Cc, Cc);
        // Attention (1 warp per row; 4 warps per block)
        attn_kernel<<<(Bb * Hh * Tt) / 4, 128>>>(qkv, seq_ls, y);
        // Attn out-proj + residual
        gemm_kernel<false, true><<<dim3(Cc / 64, Mrows / 64), 256>>>(
            y, attnp_w + (size_t)l * Cc * Cc, attnp_b + (size_t)l * Cc,
            x, x, Mrows, Cc, Cc);
        // LN2
        ln_kernel<<<Mrows, 256>>>(x, ln2_s + l * Cc, ln2_b + l * Cc, h);
        // FC + ReLU [2048,1024] x [1024,4096]
        gemm_kernel<true, false><<<dim3(4 * Cc / 64, Mrows / 64), 256>>>(
            h, fc_w + (size_t)l * Cc * 4 * Cc, fc_b + (size_t)l * 4 * Cc,
            nullptr, fc, Mrows, 4 * Cc, Cc);
        // MLP proj + residual [2048,4096] x [4096,1024]
        gemm_kernel<false, true><<<dim3(Cc / 64, Mrows / 64), 256>>>(
            fc, proj_w + (size_t)l * 4 * Cc * Cc, proj_b + (size_t)l * Cc,
            x, x, Mrows, Cc, 4 * Cc);
    }

    // Final LN + head
    ln_kernel<<<Mrows, 256>>>(x, lnf_s, lnf_b, h);
    head_kernel<<<Mrows, 128>>>(h, head_w, out);
}

// round 2
// speedup vs baseline: 1.7891x; 1.7891x over previous
#include <cuda_runtime.h>
#include <cuda_bf16.h>
#include <math.h>

// Problem constants
#define Bb 4
#define Tt 512
#define Cc 1024
#define Hh 16
#define Ll 8
#define FSs 64
#define Vv 3
#define Dd 64          // head dim
#define Mrows (Bb*Tt)  // 2048

// ---------------------------------------------------------------------------
// Device-global scratch (no allocations allowed)
// ---------------------------------------------------------------------------
__device__ float g_x  [Mrows * Cc];        // residual stream
__device__ float g_h  [Mrows * Cc];        // LN output / final LN
__device__ float g_qkv[Mrows * 3 * Cc];    // qkv
__device__ float g_y  [Mrows * Cc];        // attention output
__device__ float g_fc [Mrows * 4 * Cc];    // MLP hidden

// ---------------------------------------------------------------------------
// Embedding: x[m,c] = sum_f seqs[m,f]*wte_w[f,c] + wte_b[c] + wpe[t,c]
// ---------------------------------------------------------------------------
__global__ void embed_kernel(const float* __restrict__ seqs,
                             const float* __restrict__ wte_w,
                             const float* __restrict__ wte_b,
                             const float* __restrict__ wpe,
                             float* __restrict__ x)
{
    int m = blockIdx.x;
    int t = m % Tt;
    __shared__ float sf[FSs];
    if (threadIdx.x < FSs) sf[threadIdx.x] = seqs[m * FSs + threadIdx.x];
    __syncthreads();

    #pragma unroll
    for (int cc = 0; cc < 4; cc++) {
        int c = threadIdx.x + cc * 256;
        float acc = wte_b[c] + wpe[t * Cc + c];
        #pragma unroll 8
        for (int f = 0; f < FSs; f++)
            acc = fmaf(sf[f], wte_w[f * Cc + c], acc);
        x[m * Cc + c] = acc;
    }
}

// ---------------------------------------------------------------------------
// LayerNorm: one block per row (C=1024), 256 threads, 4 elems/thread.
// ---------------------------------------------------------------------------
__global__ void ln_kernel(const float* __restrict__ x,
                          const float* __restrict__ s,
                          const float* __restrict__ b,
                          float* __restrict__ out)
{
    int row = blockIdx.x;
    int tid = threadIdx.x;
    const float* xr = x + (size_t)row * Cc;

    float4 v = *(const float4*)(xr + tid * 4);
    float sum = v.x + v.y + v.z + v.w;
    float sumsq = v.x*v.x + v.y*v.y + v.z*v.z + v.w*v.w;

    // warp reduce then block reduce
    #pragma unroll
    for (int off = 16; off > 0; off >>= 1) {
        sum   += __shfl_xor_sync(0xffffffffu, sum, off);
        sumsq += __shfl_xor_sync(0xffffffffu, sumsq, off);
    }
    __shared__ float red1[8], red2[8];
    int wid = tid >> 5, lane = tid & 31;
    if (lane == 0) { red1[wid] = sum; red2[wid] = sumsq; }
    __syncthreads();
    if (wid == 0) {
        float s1 = red1[lane & 7], s2 = red2[lane & 7];
        #pragma unroll
        for (int off = 4; off > 0; off >>= 1) {
            s1 += __shfl_xor_sync(0xffffffffu, s1, off);
            s2 += __shfl_xor_sync(0xffffffffu, s2, off);
        }
        if (lane == 0) { red1[0] = s1; red2[0] = s2; }
    }
    __syncthreads();
    float mean = red1[0] * (1.0f / Cc);
    float var  = red2[0] * (1.0f / Cc) - mean * mean;
    float rstd = rsqrtf(var + 1e-5f);

    int c = tid * 4;
    float4 sv = *(const float4*)(s + c);
    float4 bv = *(const float4*)(b + c);
    float4 o;
    o.x = (v.x - mean) * rstd * sv.x + bv.x;
    o.y = (v.y - mean) * rstd * sv.y + bv.y;
    o.z = (v.z - mean) * rstd * sv.z + bv.z;
    o.w = (v.w - mean) * rstd * sv.w + bv.w;
    *(float4*)(out + (size_t)row * Cc + c) = o;
}

// ---------------------------------------------------------------------------
// SGEMM 128x128x8, double-buffered, 256 threads, 8x8 micro-tile.
// C = A[M,K] @ B[K,N] + bias (+ residual) (optional ReLU). Dims divisible.
// ---------------------------------------------------------------------------
template <bool RELU, bool RES>
__global__ void __launch_bounds__(256, 2)
gemm_kernel(const float* __restrict__ A,
            const float* __restrict__ Bm,
            const float* __restrict__ bias,
            const float* __restrict__ res,
            float* __restrict__ C,
            int M, int N, int K)
{
    const int BM = 128, BN = 128, BK = 8;
    __shared__ float As[2][BK][BM];
    __shared__ float Bs[2][BK][BN];

    int tid = threadIdx.x;
    int blockRow = blockIdx.y * BM;
    int blockCol = blockIdx.x * BN;

    // A tile load mapping: 128 rows x 8 cols = 1024 floats = 256 x float4
    int aRow = tid >> 1;             // 0..127
    int aCol = (tid & 1) * 4;        // 0 or 4
    // B tile load mapping: 8 rows x 128 cols
    int bRow = tid >> 5;             // 0..7
    int bCol = (tid & 31) * 4;       // 0..124

    const float* Aptr = A + (size_t)(blockRow + aRow) * K + aCol;
    const float* Bptr = Bm + (size_t)bRow * N + blockCol + bCol;

    // prologue: load tile 0
    float4 a4 = *(const float4*)Aptr;
    float4 b4 = *(const float4*)Bptr;
    As[0][aCol + 0][aRow] = a4.x;
    As[0][aCol + 1][aRow] = a4.y;
    As[0][aCol + 2][aRow] = a4.z;
    As[0][aCol + 3][aRow] = a4.w;
    *(float4*)&Bs[0][bRow][bCol] = b4;
    __syncthreads();

    int tr = tid >> 4;   // 0..15
    int tc = tid & 15;   // 0..15

    float acc[8][8] = {};
    int nk = K / BK;
    int buf = 0;

    for (int kt = 0; kt < nk; kt++) {
        // prefetch next tile into registers
        if (kt + 1 < nk) {
            a4 = *(const float4*)(Aptr + (kt + 1) * BK);
            b4 = *(const float4*)(Bptr + (size_t)(kt + 1) * BK * N);
        }

        #pragma unroll
        for (int kk = 0; kk < BK; kk++) {
            float a[8], bq[8];
            *(float4*)&a[0]  = *(const float4*)&As[buf][kk][tr * 8];
            *(float4*)&a[4]  = *(const float4*)&As[buf][kk][tr * 8 + 4];
            *(float4*)&bq[0] = *(const float4*)&Bs[buf][kk][tc * 8];
            *(float4*)&bq[4] = *(const float4*)&Bs[buf][kk][tc * 8 + 4];
            #pragma unroll
            for (int i = 0; i < 8; i++)
                #pragma unroll
                for (int j = 0; j < 8; j++)
                    acc[i][j] = fmaf(a[i], bq[j], acc[i][j]);
        }

        if (kt + 1 < nk) {
            int nb = buf ^ 1;
            As[nb][aCol + 0][aRow] = a4.x;
            As[nb][aCol + 1][aRow] = a4.y;
            As[nb][aCol + 2][aRow] = a4.z;
            As[nb][aCol + 3][aRow] = a4.w;
            *(float4*)&Bs[nb][bRow][bCol] = b4;
            __syncthreads();
            buf = nb;
        }
    }

    // epilogue
    #pragma unroll
    for (int i = 0; i < 8; i++) {
        size_t row = blockRow + tr * 8 + i;
        #pragma unroll
        for (int j4 = 0; j4 < 8; j4 += 4) {
            int col = blockCol + tc * 8 + j4;
            float4 bv = *(const float4*)(bias + col);
            float4 o;
            o.x = acc[i][j4 + 0] + bv.x;
            o.y = acc[i][j4 + 1] + bv.y;
            o.z = acc[i][j4 + 2] + bv.z;
            o.w = acc[i][j4 + 3] + bv.w;
            if (RES) {
                float4 rv = *(const float4*)(res + row * N + col);
                o.x += rv.x; o.y += rv.y; o.z += rv.z; o.w += rv.w;
            }
            if (RELU) {
                o.x = fmaxf(o.x, 0.f); o.y = fmaxf(o.y, 0.f);
                o.z = fmaxf(o.z, 0.f); o.w = fmaxf(o.w, 0.f);
            }
            *(float4*)(C + row * N + col) = o;
        }
    }
}

// ---------------------------------------------------------------------------
// Attention: block per (b, h, 8-query tile). 256 threads = 8 warps, 1 query
// per warp. K/V staged in smem in 32-key tiles; K stored transposed (pad 33).
// Lanes-over-keys: lane l owns score for key j0+l.
// ---------------------------------------------------------------------------
__global__ void __launch_bounds__(256, 4)
attn_kernel(const float* __restrict__ qkv,
            const int* __restrict__ seq_ls,
            float* __restrict__ y)
{
    const int QTILE = 8;
    int warp = threadIdx.x >> 5;
    int lane = threadIdx.x & 31;
    int qb = blockIdx.x % (Tt / QTILE);
    int h  = (blockIdx.x / (Tt / QTILE)) % Hh;
    int b  = blockIdx.x / ((Tt / QTILE) * Hh);
    int t  = qb * QTILE + warp;

    __shared__ float Kst[Dd][33];   // transposed K tile (dim-major)
    __shared__ float Vs[32][Dd];    // V tile (key-major)

    int lv = seq_ls[b];

    // query: lane holds dims lane and lane+32 (for scores),
    // accumulator holds dims 2*lane, 2*lane+1 (for output)
    const float* qrow = qkv + ((size_t)(b * Tt + t)) * (3 * Cc) + h * Dd;
    float qa = qrow[lane];
    float qb_ = qrow[lane + 32];

    const float* kbase = qkv + (size_t)b * Tt * 3 * Cc + Cc + h * Dd;
    const float* vbase = kbase + Cc;

    float mmax = -INFINITY, lsum = 0.f;
    float2 acc = make_float2(0.f, 0.f);

    for (int j0 = 0; j0 < lv; j0 += 32) {
        __syncthreads();   // previous tile fully consumed
        // cooperative load: 256 threads, 32 keys x 64 dims for K and V
        {
            int key = threadIdx.x >> 3;          // 0..31
            int d0  = (threadIdx.x & 7) * 8;     // 0,8,...,56
            int j = j0 + key;
            float4 k0v, k1v, v0v, v1v;
            if (j < lv) {
                const float* kr = kbase + (size_t)j * (3 * Cc);
                k0v = *(const float4*)(kr + d0);
                k1v = *(const float4*)(kr + d0 + 4);
                const float* vr = vbase + (size_t)j * (3 * Cc);
                v0v = *(const float4*)(vr + d0);
                v1v = *(const float4*)(vr + d0 + 4);
            } else {
                k0v = k1v = v0v = v1v = make_float4(0.f, 0.f, 0.f, 0.f);
            }
            Kst[d0 + 0][key] = k0v.x; Kst[d0 + 1][key] = k0v.y;
            Kst[d0 + 2][key] = k0v.z; Kst[d0 + 3][key] = k0v.w;
            Kst[d0 + 4][key] = k1v.x; Kst[d0 + 5][key] = k1v.y;
            Kst[d0 + 6][key] = k1v.z; Kst[d0 + 7][key] = k1v.w;
            *(float4*)&Vs[key][d0]     = v0v;
            *(float4*)&Vs[key][d0 + 4] = v1v;
        }
        __syncthreads();

        // score for this lane's key
        float s = 0.f;
        #pragma unroll
        for (int dsrc = 0; dsrc < 32; dsrc++) {
            float q1 = __shfl_sync(0xffffffffu, qa,  dsrc);
            float q2 = __shfl_sync(0xffffffffu, qb_, dsrc);
            s = fmaf(q1, Kst[dsrc][lane], s);
            s = fmaf(q2, Kst[dsrc + 32][lane], s);
        }
        s *= 0.125f;
        if (j0 + lane >= lv) s = -INFINITY;

        // online softmax update
        float smax = s;
        #pragma unroll
        for (int off = 16; off > 0; off >>= 1)
            smax = fmaxf(smax, __shfl_xor_sync(0xffffffffu, smax, off));
        float mnew = fmaxf(mmax, smax);
        float corr = __expf(mmax - mnew);
        float p = __expf(s - mnew);     // 0 for invalid lanes
        float psum = p;
        #pragma unroll
        for (int off = 16; off > 0; off >>= 1)
            psum += __shfl_xor_sync(0xffffffffu, psum, off);
        lsum = lsum * corr + psum;
        acc.x *= corr; acc.y *= corr;

        #pragma unroll
        for (int src = 0; src < 32; src++) {
            float pp = __shfl_sync(0xffffffffu, p, src);
            float2 vv = *(const float2*)&Vs[src][2 * lane];
            acc.x = fmaf(pp, vv.x, acc.x);
            acc.y = fmaf(pp, vv.y, acc.y);
        }
        mmax = mnew;
    }

    float inv = 1.0f / lsum;
    float* yrow = y + ((size_t)(b * Tt + t)) * Cc + h * Dd;
    *(float2*)(yrow + 2 * lane) = make_float2(acc.x * inv, acc.y * inv);
}

// ---------------------------------------------------------------------------
// Head: logits[m, v] = sum_k xf[m,k]*hw[k,v]; V=3.
// ---------------------------------------------------------------------------
__global__ void head_kernel(const float* __restrict__ xf,
                            const float* __restrict__ hw,
                            float* __restrict__ out)
{
    int row = blockIdx.x;
    int tid = threadIdx.x;
    float a0 = 0.f, a1 = 0.f, a2 = 0.f;
    const float* xr = xf + (size_t)row * Cc;
    for (int k = tid; k < Cc; k += 128) {
        float xv = xr[k];
        a0 = fmaf(xv, hw[k * 3 + 0], a0);
        a1 = fmaf(xv, hw[k * 3 + 1], a1);
        a2 = fmaf(xv, hw[k * 3 + 2], a2);
    }
    __shared__ float r0[128], r1[128], r2[128];
    r0[tid] = a0; r1[tid] = a1; r2[tid] = a2;
    __syncthreads();
    for (int off = 64; off > 0; off >>= 1) {
        if (tid < off) { r0[tid] += r0[tid+off]; r1[tid] += r1[tid+off]; r2[tid] += r2[tid+off]; }
        __syncthreads();
    }
    if (tid == 0) {
        out[row * 3 + 0] = r0[0];
        out[row * 3 + 1] = r1[0];
        out[row * 3 + 2] = r2[0];
    }
}

// ---------------------------------------------------------------------------
// Launch
// ---------------------------------------------------------------------------
extern "C" void kernel_launch(void* const* d_in, const int* in_sizes, int n_in,
                              void* d_out, int out_size)
{
    const float* seqs    = (const float*)d_in[0];
    const int*   seq_ls  = (const int*)  d_in[1];
    const float* wte_w   = (const float*)d_in[2];
    const float* wte_b   = (const float*)d_in[3];
    const float* wpe     = (const float*)d_in[4];
    const float* ln1_s   = (const float*)d_in[5];
    const float* ln1_b   = (const float*)d_in[6];
    const float* attn_w  = (const float*)d_in[7];
    const float* attn_b  = (const float*)d_in[8];
    const float* attnp_w = (const float*)d_in[9];
    const float* attnp_b = (const float*)d_in[10];
    const float* ln2_s   = (const float*)d_in[11];
    const float* ln2_b   = (const float*)d_in[12];
    const float* fc_w    = (const float*)d_in[13];
    const float* fc_b    = (const float*)d_in[14];
    const float* proj_w  = (const float*)d_in[15];
    const float* proj_b  = (const float*)d_in[16];
    const float* lnf_s   = (const float*)d_in[17];
    const float* lnf_b   = (const float*)d_in[18];
    const float* head_w  = (const float*)d_in[19];
    float* out = (float*)d_out;

    float *x, *h, *qkv, *y, *fc;
    cudaGetSymbolAddress((void**)&x,   g_x);
    cudaGetSymbolAddress((void**)&h,   g_h);
    cudaGetSymbolAddress((void**)&qkv, g_qkv);
    cudaGetSymbolAddress((void**)&y,   g_y);
    cudaGetSymbolAddress((void**)&fc,  g_fc);

    // Embedding
    embed_kernel<<<Mrows, 256>>>(seqs, wte_w, wte_b, wpe, x);

    for (int l = 0; l < Ll; l++) {
        // LN1
        ln_kernel<<<Mrows, 256>>>(x, ln1_s + l * Cc, ln1_b + l * Cc, h);
        // QKV GEMM [2048,1024] x [1024,3072]
        gemm_kernel<false, false><<<dim3(3 * Cc / 128, Mrows / 128), 256>>>(
            h, attn_w + (size_t)l * Cc * 3 * Cc, attn_b + (size_t)l * 3 * Cc,
            nullptr, qkv, Mrows, 3 * Cc, Cc);
        // Attention: block per (b,h,8 queries)
        attn_kernel<<<Bb * Hh * (Tt / 8), 256>>>(qkv, seq_ls, y);
        // Attn out-proj + residual
        gemm_kernel<false, true><<<dim3(Cc / 128, Mrows / 128), 256>>>(
            y, attnp_w + (size_t)l * Cc * Cc, attnp_b + (size_t)l * Cc,
            x, x, Mrows, Cc, Cc);
        // LN2
        ln_kernel<<<Mrows, 256>>>(x, ln2_s + l * Cc, ln2_b + l * Cc, h);
        // FC + ReLU [2048,1024] x [1024,4096]
        gemm_kernel<true, false><<<dim3(4 * Cc / 128, Mrows / 128), 256>>>(
            h, fc_w + (size_t)l * Cc * 4 * Cc, fc_b + (size_t)l * 4 * Cc,
            nullptr, fc, Mrows, 4 * Cc, Cc);
        // MLP proj + residual [2048,4096] x [4096,1024]
        gemm_kernel<false, true><<<dim3(Cc / 128, Mrows / 128), 256>>>(
            fc, proj_w + (size_t)l * 4 * Cc * Cc, proj_b + (size_t)l * Cc,
            x, x, Mrows, Cc, 4 * Cc);
    }

    // Final LN + head
    ln_kernel<<<Mrows, 256>>>(x, lnf_s, lnf_b, h);
    head_kernel<<<Mrows, 128>>>(h, head_w, out);
}

// round 3
// speedup vs baseline: 3.2267x; 1.8036x over previous
#include <cuda_runtime.h>
#include <cuda_bf16.h>
#include <math.h>

// Problem constants
#define Bb 4
#define Tt 512
#define Cc 1024
#define Hh 16
#define Ll 8
#define FSs 64
#define Vv 3
#define Dd 64          // head dim
#define Mrows (Bb*Tt)  // 2048

// ---------------------------------------------------------------------------
// Device-global scratch (no allocations allowed)
// ---------------------------------------------------------------------------
__device__ float g_x  [Mrows * Cc];        // residual stream
__device__ float g_h  [Mrows * Cc];        // LN output
__device__ float g_qkv[Mrows * 3 * Cc];    // qkv
__device__ float g_y  [Mrows * Cc];        // attention output
__device__ float g_fc [Mrows * 4 * Cc];    // MLP hidden

// ---------------------------------------------------------------------------
// Helpers
// ---------------------------------------------------------------------------
__device__ __forceinline__ unsigned f2tf32(float x) {
    unsigned r;
    asm("cvt.rna.tf32.f32 %0, %1;" : "=r"(r) : "f"(x));
    return r;
}

__device__ __forceinline__ void mma_tf32(float c[4], const unsigned a[4],
                                         unsigned b0, unsigned b1) {
    asm volatile(
        "mma.sync.aligned.m16n8k8.row.col.f32.tf32.tf32.f32 "
        "{%0,%1,%2,%3}, {%4,%5,%6,%7}, {%8,%9}, {%0,%1,%2,%3};"
        : "+f"(c[0]), "+f"(c[1]), "+f"(c[2]), "+f"(c[3])
        : "r"(a[0]), "r"(a[1]), "r"(a[2]), "r"(a[3]), "r"(b0), "r"(b1));
}

// ---------------------------------------------------------------------------
// Embedding
// ---------------------------------------------------------------------------
__global__ void embed_kernel(const float* __restrict__ seqs,
                             const float* __restrict__ wte_w,
                             const float* __restrict__ wte_b,
                             const float* __restrict__ wpe,
                             float* __restrict__ x)
{
    int m = blockIdx.x;
    int t = m % Tt;
    __shared__ float sf[FSs];
    if (threadIdx.x < FSs) sf[threadIdx.x] = seqs[m * FSs + threadIdx.x];
    __syncthreads();

    #pragma unroll
    for (int cc = 0; cc < 4; cc++) {
        int c = threadIdx.x + cc * 256;
        float acc = wte_b[c] + wpe[t * Cc + c];
        #pragma unroll 8
        for (int f = 0; f < FSs; f++)
            acc = fmaf(sf[f], wte_w[f * Cc + c], acc);
        x[m * Cc + c] = acc;
    }
}

// ---------------------------------------------------------------------------
// LayerNorm: one block per row (C=1024), 256 threads, 4 elems/thread.
// ---------------------------------------------------------------------------
__global__ void ln_kernel(const float* __restrict__ x,
                          const float* __restrict__ s,
                          const float* __restrict__ b,
                          float* __restrict__ out)
{
    int row = blockIdx.x;
    int tid = threadIdx.x;
    const float* xr = x + (size_t)row * Cc;

    float4 v = *(const float4*)(xr + tid * 4);
    float sum = v.x + v.y + v.z + v.w;
    float sumsq = v.x*v.x + v.y*v.y + v.z*v.z + v.w*v.w;

    #pragma unroll
    for (int off = 16; off > 0; off >>= 1) {
        sum   += __shfl_xor_sync(0xffffffffu, sum, off);
        sumsq += __shfl_xor_sync(0xffffffffu, sumsq, off);
    }
    __shared__ float red1[8], red2[8];
    int wid = tid >> 5, lane = tid & 31;
    if (lane == 0) { red1[wid] = sum; red2[wid] = sumsq; }
    __syncthreads();
    if (wid == 0) {
        float s1 = red1[lane & 7], s2 = red2[lane & 7];
        #pragma unroll
        for (int off = 4; off > 0; off >>= 1) {
            s1 += __shfl_xor_sync(0xffffffffu, s1, off);
            s2 += __shfl_xor_sync(0xffffffffu, s2, off);
        }
        if (lane == 0) { red1[0] = s1; red2[0] = s2; }
    }
    __syncthreads();
    float mean = red1[0] * (1.0f / Cc);
    float var  = red2[0] * (1.0f / Cc) - mean * mean;
    float rstd = rsqrtf(var + 1e-5f);

    int c = tid * 4;
    float4 sv = *(const float4*)(s + c);
    float4 bv = *(const float4*)(b + c);
    float4 o;
    o.x = (v.x - mean) * rstd * sv.x + bv.x;
    o.y = (v.y - mean) * rstd * sv.y + bv.y;
    o.z = (v.z - mean) * rstd * sv.z + bv.z;
    o.w = (v.w - mean) * rstd * sv.w + bv.w;
    *(float4*)(out + (size_t)row * Cc + c) = o;
}

// ---------------------------------------------------------------------------
// TF32 tensor-core GEMM: C = A[M,K] @ B[K,N] + bias (+res) (opt ReLU).
// 128x128x16 tiles, double-buffered smem, 8 warps (4x2), warp tile 32x64.
// mma.m16n8k8.tf32, fp32 accumulate. Dims divisible by tiles.
// ---------------------------------------------------------------------------
#define LDT 136   // smem row stride (words): k-major, conflict-free frag loads

template <bool RELU, bool RES>
__global__ void __launch_bounds__(256, 2)
gemm_tc(const float* __restrict__ A,
        const float* __restrict__ Bm,
        const float* __restrict__ bias,
        const float* __restrict__ res,
        float* __restrict__ C,
        int M, int N, int K)
{
    const int BK = 16;
    __shared__ float As[2][BK][LDT];   // As[k][m], m:0..127
    __shared__ float Bs[2][BK][LDT];   // Bs[k][n], n:0..127

    int tid = threadIdx.x;
    int lane = tid & 31;
    int warp = tid >> 5;
    int blockRow = blockIdx.y * 128;
    int blockCol = blockIdx.x * 128;

    // ---- global load mappings ----
    // A tile: 128 rows x 16 cols. thread: row=(tid&63)+64p, col=(tid>>6)*4
    int aRow = tid & 63;
    int aCol = (tid >> 6) * 4;
    const float* Aptr = A + (size_t)(blockRow + aRow) * K + aCol;
    // B tile: 16 rows x 128 cols. thread: krow=(tid>>5)+8p, col=(tid&31)*4
    int bRow = tid >> 5;
    int bCol = (tid & 31) * 4;
    const float* Bptr = Bm + (size_t)bRow * N + blockCol + bCol;

    float4 a4[2], b4[2];
    // prologue: tile 0
    a4[0] = *(const float4*)Aptr;
    a4[1] = *(const float4*)(Aptr + (size_t)64 * K);
    b4[0] = *(const float4*)Bptr;
    b4[1] = *(const float4*)(Bptr + (size_t)8 * N);
    #pragma unroll
    for (int p = 0; p < 2; p++) {
        float vv[4] = {a4[p].x, a4[p].y, a4[p].z, a4[p].w};
        #pragma unroll
        for (int i = 0; i < 4; i++)
            As[0][aCol + i][aRow + 64 * p] = __uint_as_float(f2tf32(vv[i]));
        float wv[4] = {b4[p].x, b4[p].y, b4[p].z, b4[p].w};
        #pragma unroll
        for (int i = 0; i < 4; i++)
            Bs[0][bRow + 8 * p][bCol + i] = __uint_as_float(f2tf32(wv[i]));
    }
    __syncthreads();

    // warp layout: 4 (m) x 2 (n)
    int m0 = (warp >> 1) * 32;
    int n0 = (warp & 1) * 64;
    int g  = lane >> 2;      // 0..7
    int tg = lane & 3;       // 0..3

    float acc[2][8][4];
    #pragma unroll
    for (int mt = 0; mt < 2; mt++)
        #pragma unroll
        for (int nt = 0; nt < 8; nt++)
            #pragma unroll
            for (int i = 0; i < 4; i++) acc[mt][nt][i] = 0.f;

    int nk = K / BK;
    int buf = 0;

    for (int kt = 0; kt < nk; kt++) {
        if (kt + 1 < nk) {
            a4[0] = *(const float4*)(Aptr + (kt + 1) * BK);
            a4[1] = *(const float4*)(Aptr + (size_t)64 * K + (kt + 1) * BK);
            b4[0] = *(const float4*)(Bptr + (size_t)(kt + 1) * BK * N);
            b4[1] = *(const float4*)(Bptr + (size_t)((kt + 1) * BK + 8) * N);
        }

        #pragma unroll
        for (int ks = 0; ks < BK; ks += 8) {
            unsigned af[2][4];
            #pragma unroll
            for (int mt = 0; mt < 2; mt++) {
                int m = m0 + mt * 16 + g;
                af[mt][0] = __float_as_uint(As[buf][ks + tg][m]);
                af[mt][1] = __float_as_uint(As[buf][ks + tg][m + 8]);
                af[mt][2] = __float_as_uint(As[buf][ks + tg + 4][m]);
                af[mt][3] = __float_as_uint(As[buf][ks + tg + 4][m + 8]);
            }
            #pragma unroll
            for (int nt = 0; nt < 8; nt++) {
                int n = n0 + nt * 8 + g;
                unsigned b0 = __float_as_uint(Bs[buf][ks + tg][n]);
                unsigned b1 = __float_as_uint(Bs[buf][ks + tg + 4][n]);
                mma_tf32(acc[0][nt], af[0], b0, b1);
                mma_tf32(acc[1][nt], af[1], b0, b1);
            }
        }

        if (kt + 1 < nk) {
            int nb = buf ^ 1;
            #pragma unroll
            for (int p = 0; p < 2; p++) {
                float vv[4] = {a4[p].x, a4[p].y, a4[p].z, a4[p].w};
                #pragma unroll
                for (int i = 0; i < 4; i++)
                    As[nb][aCol + i][aRow + 64 * p] = __uint_as_float(f2tf32(vv[i]));
                float wv[4] = {b4[p].x, b4[p].y, b4[p].z, b4[p].w};
                #pragma unroll
                for (int i = 0; i < 4; i++)
                    Bs[nb][bRow + 8 * p][bCol + i] = __uint_as_float(f2tf32(wv[i]));
            }
            __syncthreads();
            buf = nb;
        }
    }

    // epilogue
    #pragma unroll
    for (int mt = 0; mt < 2; mt++) {
        #pragma unroll
        for (int nt = 0; nt < 8; nt++) {
            int col = blockCol + n0 + nt * 8 + tg * 2;
            size_t r0 = blockRow + m0 + mt * 16 + g;
            size_t r1 = r0 + 8;
            float b0v = bias[col], b1v = bias[col + 1];
            float2 o0 = make_float2(acc[mt][nt][0] + b0v, acc[mt][nt][1] + b1v);
            float2 o1 = make_float2(acc[mt][nt][2] + b0v, acc[mt][nt][3] + b1v);
            if (RES) {
                float2 rv0 = *(const float2*)(res + r0 * N + col);
                float2 rv1 = *(const float2*)(res + r1 * N + col);
                o0.x += rv0.x; o0.y += rv0.y;
                o1.x += rv1.x; o1.y += rv1.y;
            }
            if (RELU) {
                o0.x = fmaxf(o0.x, 0.f); o0.y = fmaxf(o0.y, 0.f);
                o1.x = fmaxf(o1.x, 0.f); o1.y = fmaxf(o1.y, 0.f);
            }
            *(float2*)(C + r0 * N + col) = o0;
            *(float2*)(C + r1 * N + col) = o1;
        }
    }
}

// ---------------------------------------------------------------------------
// Attention: block per (b, h, 8-query tile). 8 warps, 1 query per warp.
// K transposed in smem (pad 33), q & p broadcast via smem (no data shuffles).
// ---------------------------------------------------------------------------
__global__ void __launch_bounds__(256, 4)
attn_kernel(const float* __restrict__ qkv,
            const int* __restrict__ seq_ls,
            float* __restrict__ y)
{
    const int QTILE = 8;
    int warp = threadIdx.x >> 5;
    int lane = threadIdx.x & 31;
    int qb = blockIdx.x % (Tt / QTILE);
    int h  = (blockIdx.x / (Tt / QTILE)) % Hh;
    int b  = blockIdx.x / ((Tt / QTILE) * Hh);
    int t  = qb * QTILE + warp;

    __shared__ float Kst[Dd][33];   // transposed K tile (dim-major)
    __shared__ float Vs[32][Dd];    // V tile (key-major)
    __shared__ float qs[QTILE][Dd]; // per-warp query
    __shared__ float ps[QTILE][32]; // per-warp probabilities

    int lv = seq_ls[b];

    const float* qrow = qkv + ((size_t)(b * Tt + t)) * (3 * Cc) + h * Dd;
    qs[warp][lane]      = qrow[lane];
    qs[warp][lane + 32] = qrow[lane + 32];
    __syncwarp();

    const float* kbase = qkv + (size_t)b * Tt * 3 * Cc + Cc + h * Dd;
    const float* vbase = kbase + Cc;

    float mmax = -INFINITY, lsum = 0.f;
    float2 acc = make_float2(0.f, 0.f);

    for (int j0 = 0; j0 < lv; j0 += 32) {
        __syncthreads();   // previous tile fully consumed
        {
            int key = threadIdx.x >> 3;          // 0..31
            int d0  = (threadIdx.x & 7) * 8;     // 0,8,...,56
            int j = j0 + key;
            float4 k0v, k1v, v0v, v1v;
            if (j < lv) {
                const float* kr = kbase + (size_t)j * (3 * Cc);
                k0v = *(const float4*)(kr + d0);
                k1v = *(const float4*)(kr + d0 + 4);
                const float* vr = vbase + (size_t)j * (3 * Cc);
                v0v = *(const float4*)(vr + d0);
                v1v = *(const float4*)(vr + d0 + 4);
            } else {
                k0v = k1v = v0v = v1v = make_float4(0.f, 0.f, 0.f, 0.f);
            }
            Kst[d0 + 0][key] = k0v.x; Kst[d0 + 1][key] = k0v.y;
            Kst[d0 + 2][key] = k0v.z; Kst[d0 + 3][key] = k0v.w;
            Kst[d0 + 4][key] = k1v.x; Kst[d0 + 5][key] = k1v.y;
            Kst[d0 + 6][key] = k1v.z; Kst[d0 + 7][key] = k1v.w;
            *(float4*)&Vs[key][d0]     = v0v;
            *(float4*)&Vs[key][d0 + 4] = v1v;
        }
        __syncthreads();

        // score for this lane's key: q (smem broadcast) . K^T (conflict-free)
        float s = 0.f;
        #pragma unroll
        for (int d = 0; d < Dd; d++)
            s = fmaf(qs[warp][d], Kst[d][lane], s);
        s *= 0.125f;
        if (j0 + lane >= lv) s = -INFINITY;

        // online softmax update
        float smax = s;
        #pragma unroll
        for (int off = 16; off > 0; off >>= 1)
            smax = fmaxf(smax, __shfl_xor_sync(0xffffffffu, smax, off));
        float mnew = fmaxf(mmax, smax);
        float corr = __expf(mmax - mnew);
        float p = __expf(s - mnew);     // 0 for invalid lanes
        float psum = p;
        #pragma unroll
        for (int off = 16; off > 0; off >>= 1)
            psum += __shfl_xor_sync(0xffffffffu, psum, off);
        lsum = lsum * corr + psum;
        acc.x *= corr; acc.y *= corr;

        ps[warp][lane] = p;
        __syncwarp();

        #pragma unroll
        for (int src = 0; src < 32; src++) {
            float pp = ps[warp][src];
            float2 vv = *(const float2*)&Vs[src][2 * lane];
            acc.x = fmaf(pp, vv.x, acc.x);
            acc.y = fmaf(pp, vv.y, acc.y);
        }
        mmax = mnew;
    }

    float inv = 1.0f / lsum;
    float* yrow = y + ((size_t)(b * Tt + t)) * Cc + h * Dd;
    *(float2*)(yrow + 2 * lane) = make_float2(acc.x * inv, acc.y * inv);
}

// ---------------------------------------------------------------------------
// Head: logits[m, v] = sum_k xf[m,k]*hw[k,v]; V=3.
// ---------------------------------------------------------------------------
__global__ void head_kernel(const float* __restrict__ xf,
                            const float* __restrict__ hw,
                            float* __restrict__ out)
{
    int row = blockIdx.x;
    int tid = threadIdx.x;
    float a0 = 0.f, a1 = 0.f, a2 = 0.f;
    const float* xr = xf + (size_t)row * Cc;
    for (int k = tid; k < Cc; k += 128) {
        float xv = xr[k];
        a0 = fmaf(xv, hw[k * 3 + 0], a0);
        a1 = fmaf(xv, hw[k * 3 + 1], a1);
        a2 = fmaf(xv, hw[k * 3 + 2], a2);
    }
    __shared__ float r0[128], r1[128], r2[128];
    r0[tid] = a0; r1[tid] = a1; r2[tid] = a2;
    __syncthreads();
    for (int off = 64; off > 0; off >>= 1) {
        if (tid < off) { r0[tid] += r0[tid+off]; r1[tid] += r1[tid+off]; r2[tid] += r2[tid+off]; }
        __syncthreads();
    }
    if (tid == 0) {
        out[row * 3 + 0] = r0[0];
        out[row * 3 + 1] = r1[0];
        out[row * 3 + 2] = r2[0];
    }
}

// ---------------------------------------------------------------------------
// Launch
// ---------------------------------------------------------------------------
extern "C" void kernel_launch(void* const* d_in, const int* in_sizes, int n_in,
                              void* d_out, int out_size)
{
    const float* seqs    = (const float*)d_in[0];
    const int*   seq_ls  = (const int*)  d_in[1];
    const float* wte_w   = (const float*)d_in[2];
    const float* wte_b   = (const float*)d_in[3];
    const float* wpe     = (const float*)d_in[4];
    const float* ln1_s   = (const float*)d_in[5];
    const float* ln1_b   = (const float*)d_in[6];
    const float* attn_w  = (const float*)d_in[7];
    const float* attn_b  = (const float*)d_in[8];
    const float* attnp_w = (const float*)d_in[9];
    const float* attnp_b = (const float*)d_in[10];
    const float* ln2_s   = (const float*)d_in[11];
    const float* ln2_b   = (const float*)d_in[12];
    const float* fc_w    = (const float*)d_in[13];
    const float* fc_b    = (const float*)d_in[14];
    const float* proj_w  = (const float*)d_in[15];
    const float* proj_b  = (const float*)d_in[16];
    const float* lnf_s   = (const float*)d_in[17];
    const float* lnf_b   = (const float*)d_in[18];
    const float* head_w  = (const float*)d_in[19];
    float* out = (float*)d_out;

    float *x, *h, *qkv, *y, *fc;
    cudaGetSymbolAddress((void**)&x,   g_x);
    cudaGetSymbolAddress((void**)&h,   g_h);
    cudaGetSymbolAddress((void**)&qkv, g_qkv);
    cudaGetSymbolAddress((void**)&y,   g_y);
    cudaGetSymbolAddress((void**)&fc,  g_fc);

    // Embedding
    embed_kernel<<<Mrows, 256>>>(seqs, wte_w, wte_b, wpe, x);

    for (int l = 0; l < Ll; l++) {
        // LN1
        ln_kernel<<<Mrows, 256>>>(x, ln1_s + l * Cc, ln1_b + l * Cc, h);
        // QKV GEMM [2048,1024] x [1024,3072]
        gemm_tc<false, false><<<dim3(3 * Cc / 128, Mrows / 128), 256>>>(
            h, attn_w + (size_t)l * Cc * 3 * Cc, attn_b + (size_t)l * 3 * Cc,
            nullptr, qkv, Mrows, 3 * Cc, Cc);
        // Attention
        attn_kernel<<<Bb * Hh * (Tt / 8), 256>>>(qkv, seq_ls, y);
        // Attn out-proj + residual
        gemm_tc<false, true><<<dim3(Cc / 128, Mrows / 128), 256>>>(
            y, attnp_w + (size_t)l * Cc * Cc, attnp_b + (size_t)l * Cc,
            x, x, Mrows, Cc, Cc);
        // LN2
        ln_kernel<<<Mrows, 256>>>(x, ln2_s + l * Cc, ln2_b + l * Cc, h);
        // FC + ReLU [2048,1024] x [1024,4096]
        gemm_tc<true, false><<<dim3(4 * Cc / 128, Mrows / 128), 256>>>(
            h, fc_w + (size_t)l * Cc * 4 * Cc, fc_b + (size_t)l * 4 * Cc,
            nullptr, fc, Mrows, 4 * Cc, Cc);
        // MLP proj + residual [2048,4096] x [4096,1024]
        gemm_tc<false, true><<<dim3(Cc / 128, Mrows / 128), 256>>>(
            fc, proj_w + (size_t)l * 4 * Cc * Cc, proj_b + (size_t)l * Cc,
            x, x, Mrows, Cc, 4 * Cc);
    }

    // Final LN + head
    ln_kernel<<<Mrows, 256>>>(x, lnf_s, lnf_b, h);
    head_kernel<<<Mrows, 128>>>(h, head_w, out);
}

// round 5
// speedup vs baseline: 4.3275x; 1.3411x over previous
#include <cuda_runtime.h>
#include <cuda_bf16.h>
#include <math.h>
#include <stdint.h>

// Problem constants
#define Bb 4
#define Tt 512
#define Cc 1024
#define Hh 16
#define Ll 8
#define FSs 64
#define Vv 3
#define Dd 64          // head dim
#define Mrows (Bb*Tt)  // 2048

// ---------------------------------------------------------------------------
// Device-global scratch (no allocations allowed)
// ---------------------------------------------------------------------------
__device__ float g_x  [Mrows * Cc];        // residual stream
__device__ float g_h  [Mrows * Cc];        // LN output
__device__ float g_qkv[Mrows * 3 * Cc];    // qkv
__device__ float g_y  [Mrows * Cc];        // attention output
__device__ float g_fc [Mrows * 4 * Cc];    // MLP hidden
// tf32-pre-rounded weights (same [L][K][N] layout as inputs)
__device__ float g_wR_attn [Ll * Cc * 3 * Cc];
__device__ float g_wR_attnp[Ll * Cc * Cc];
__device__ float g_wR_fc   [Ll * Cc * 4 * Cc];
__device__ float g_wR_proj [Ll * 4 * Cc * Cc];

// ---------------------------------------------------------------------------
// Helpers
// ---------------------------------------------------------------------------
__device__ __forceinline__ unsigned f2tf32(float x) {
    unsigned r;
    asm("cvt.rna.tf32.f32 %0, %1;" : "=r"(r) : "f"(x));
    return r;
}
__device__ __forceinline__ float tf32r(float x) { return __uint_as_float(f2tf32(x)); }

__device__ __forceinline__ uint32_t smem_u32(const void* p) {
    uint32_t a;
    asm("{ .reg .u64 t; cvta.to.shared.u64 t, %1; cvt.u32.u64 %0, t; }" : "=r"(a) : "l"(p));
    return a;
}
__device__ __forceinline__ void cp_async16(uint32_t dst, const void* src) {
    asm volatile("cp.async.cg.shared.global [%0], [%1], 16;" :: "r"(dst), "l"(src));
}
#define CP_COMMIT() asm volatile("cp.async.commit_group;" ::: "memory")
#define CP_WAIT(n)  asm volatile("cp.async.wait_group %0;" :: "n"(n) : "memory")

__device__ __forceinline__ void mma_tf32(float c[4], const unsigned a[4],
                                         unsigned b0, unsigned b1) {
    asm volatile(
        "mma.sync.aligned.m16n8k8.row.col.f32.tf32.tf32.f32 "
        "{%0,%1,%2,%3}, {%4,%5,%6,%7}, {%8,%9}, {%0,%1,%2,%3};"
        : "+f"(c[0]), "+f"(c[1]), "+f"(c[2]), "+f"(c[3])
        : "r"(a[0]), "r"(a[1]), "r"(a[2]), "r"(a[3]), "r"(b0), "r"(b1));
}

// ---------------------------------------------------------------------------
// Elementwise tf32 rounding of weights (one pass, float4)
// ---------------------------------------------------------------------------
__global__ void round_w(const float* __restrict__ in, float* __restrict__ out,
                        size_t n4)
{
    size_t stride = (size_t)gridDim.x * blockDim.x;
    for (size_t i = blockIdx.x * (size_t)blockDim.x + threadIdx.x; i < n4; i += stride) {
        float4 v = ((const float4*)in)[i];
        v.x = tf32r(v.x); v.y = tf32r(v.y); v.z = tf32r(v.z); v.w = tf32r(v.w);
        ((float4*)out)[i] = v;
    }
}

// ---------------------------------------------------------------------------
// TF32 tensor-core GEMM (mma.sync), cp.async 3-stage pipeline, BK=32.
// C[M,N] = A[M,K] @ B[K,N] + bias (+res) (opt ReLU, opt tf32-round output).
// 256 threads = 8 warps (4m x 2n), warp tile 32x64. A,B pre-rounded to tf32.
// smem: As[s][128][36] (m-major), Bs[s][32][132] (k-major). Conflict-free frags.
// ---------------------------------------------------------------------------
#define LDA 36
#define LDB 132
#define A_STG (128 * LDA)
#define B_STG (32 * LDB)
#define GEMM_SMEM ((3 * (A_STG + B_STG)) * 4)

template <bool RELU, bool RES, bool ROUND>
__global__ void __launch_bounds__(256, 2)
gemm_tc(const float* __restrict__ A, const float* __restrict__ Bw,
        const float* __restrict__ bias, const float* __restrict__ res,
        float* __restrict__ C, int N, int K)
{
    extern __shared__ float sm[];
    float* Asm = sm;
    float* Bsm = sm + 3 * A_STG;

    int tid = threadIdx.x;
    int lane = tid & 31;
    int warp = tid >> 5;
    int blockRow = blockIdx.y * 128;
    int blockCol = blockIdx.x * 128;

    const float* Abase = A  + (size_t)blockRow * K;
    const float* Bbase = Bw + blockCol;
    int nk = K / 32;

    // cp.async stage loader: A tile 128x32 (1024 x 16B), B tile 32x128
    auto load_stage = [&](int kt, int s) {
        float* as = Asm + s * A_STG;
        float* bs = Bsm + s * B_STG;
        #pragma unroll
        for (int i = 0; i < 4; i++) {
            int q = tid + i * 256;
            int r = q >> 3, c = q & 7;          // A: row 0..127, 16B chunk 0..7
            cp_async16(smem_u32(as + r * LDA + c * 4),
                       Abase + (size_t)r * K + kt * 32 + c * 4);
            int k = q >> 5, c2 = q & 31;        // B: k-row 0..31, chunk 0..31
            cp_async16(smem_u32(bs + k * LDB + c2 * 4),
                       Bbase + (size_t)(kt * 32 + k) * N + c2 * 4);
        }
        CP_COMMIT();
    };

    load_stage(0, 0);
    load_stage(1, 1);

    // warp layout: 4 (m) x 2 (n)
    int m0 = (warp >> 1) * 32;
    int n0 = (warp & 1) * 64;
    int g  = lane >> 2;      // 0..7
    int tg = lane & 3;       // 0..3

    float acc[2][8][4];
    #pragma unroll
    for (int mt = 0; mt < 2; mt++)
        #pragma unroll
        for (int nt = 0; nt < 8; nt++)
            #pragma unroll
            for (int i = 0; i < 4; i++) acc[mt][nt][i] = 0.f;

    for (int kt = 0; kt < nk; kt++) {
        CP_WAIT(1);          // stage kt resident
        __syncthreads();

        const float* as = Asm + (kt % 3) * A_STG;
        const float* bs = Bsm + (kt % 3) * B_STG;

        #pragma unroll
        for (int ks = 0; ks < 32; ks += 8) {
            unsigned af[2][4];
            #pragma unroll
            for (int mt = 0; mt < 2; mt++) {
                int m = m0 + mt * 16 + g;
                af[mt][0] = __float_as_uint(as[m * LDA + ks + tg]);
                af[mt][1] = __float_as_uint(as[(m + 8) * LDA + ks + tg]);
                af[mt][2] = __float_as_uint(as[m * LDA + ks + tg + 4]);
                af[mt][3] = __float_as_uint(as[(m + 8) * LDA + ks + tg + 4]);
            }
            #pragma unroll
            for (int nt = 0; nt < 8; nt++) {
                int n = n0 + nt * 8 + g;
                unsigned b0 = __float_as_uint(bs[(ks + tg) * LDB + n]);
                unsigned b1 = __float_as_uint(bs[(ks + tg + 4) * LDB + n]);
                mma_tf32(acc[0][nt], af[0], b0, b1);
                mma_tf32(acc[1][nt], af[1], b0, b1);
            }
        }

        if (kt + 2 < nk) load_stage(kt + 2, (kt + 2) % 3);
    }

    // epilogue
    #pragma unroll
    for (int mt = 0; mt < 2; mt++) {
        #pragma unroll
        for (int nt = 0; nt < 8; nt++) {
            int col = blockCol + n0 + nt * 8 + tg * 2;
            size_t r0 = blockRow + m0 + mt * 16 + g;
            size_t r1 = r0 + 8;
            float b0v = bias[col], b1v = bias[col + 1];
            float2 o0 = make_float2(acc[mt][nt][0] + b0v, acc[mt][nt][1] + b1v);
            float2 o1 = make_float2(acc[mt][nt][2] + b0v, acc[mt][nt][3] + b1v);
            if (RES) {
                float2 rv0 = *(const float2*)(res + r0 * N + col);
                float2 rv1 = *(const float2*)(res + r1 * N + col);
                o0.x += rv0.x; o0.y += rv0.y;
                o1.x += rv1.x; o1.y += rv1.y;
            }
            if (RELU) {
                o0.x = fmaxf(o0.x, 0.f); o0.y = fmaxf(o0.y, 0.f);
                o1.x = fmaxf(o1.x, 0.f); o1.y = fmaxf(o1.y, 0.f);
            }
            if (ROUND) {
                o0.x = tf32r(o0.x); o0.y = tf32r(o0.y);
                o1.x = tf32r(o1.x); o1.y = tf32r(o1.y);
            }
            *(float2*)(C + r0 * N + col) = o0;
            *(float2*)(C + r1 * N + col) = o1;
        }
    }
}

// ---------------------------------------------------------------------------
// Embedding
// ---------------------------------------------------------------------------
__global__ void embed_kernel(const float* __restrict__ seqs,
                             const float* __restrict__ wte_w,
                             const float* __restrict__ wte_b,
                             const float* __restrict__ wpe,
                             float* __restrict__ x)
{
    int m = blockIdx.x;
    int t = m % Tt;
    __shared__ float sf[FSs];
    if (threadIdx.x < FSs) sf[threadIdx.x] = seqs[m * FSs + threadIdx.x];
    __syncthreads();

    #pragma unroll
    for (int cc = 0; cc < 4; cc++) {
        int c = threadIdx.x + cc * 256;
        float acc = wte_b[c] + wpe[t * Cc + c];
        #pragma unroll 8
        for (int f = 0; f < FSs; f++)
            acc = fmaf(sf[f], wte_w[f * Cc + c], acc);
        x[m * Cc + c] = acc;
    }
}

// ---------------------------------------------------------------------------
// LayerNorm (optionally tf32-round output when it feeds a GEMM A operand)
// ---------------------------------------------------------------------------
__global__ void ln_kernel(const float* __restrict__ x,
                          const float* __restrict__ s,
                          const float* __restrict__ b,
                          float* __restrict__ out, int rnd)
{
    int row = blockIdx.x;
    int tid = threadIdx.x;
    const float* xr = x + (size_t)row * Cc;

    float4 v = *(const float4*)(xr + tid * 4);
    float sum = v.x + v.y + v.z + v.w;
    float sumsq = v.x*v.x + v.y*v.y + v.z*v.z + v.w*v.w;

    #pragma unroll
    for (int off = 16; off > 0; off >>= 1) {
        sum   += __shfl_xor_sync(0xffffffffu, sum, off);
        sumsq += __shfl_xor_sync(0xffffffffu, sumsq, off);
    }
    __shared__ float red1[8], red2[8];
    int wid = tid >> 5, lane = tid & 31;
    if (lane == 0) { red1[wid] = sum; red2[wid] = sumsq; }
    __syncthreads();
    if (wid == 0) {
        float s1 = red1[lane & 7], s2 = red2[lane & 7];
        #pragma unroll
        for (int off = 4; off > 0; off >>= 1) {
            s1 += __shfl_xor_sync(0xffffffffu, s1, off);
            s2 += __shfl_xor_sync(0xffffffffu, s2, off);
        }
        if (lane == 0) { red1[0] = s1; red2[0] = s2; }
    }
    __syncthreads();
    float mean = red1[0] * (1.0f / Cc);
    float var  = red2[0] * (1.0f / Cc) - mean * mean;
    float rstd = rsqrtf(var + 1e-5f);

    int c = tid * 4;
    float4 sv = *(const float4*)(s + c);
    float4 bv = *(const float4*)(b + c);
    float4 o;
    o.x = (v.x - mean) * rstd * sv.x + bv.x;
    o.y = (v.y - mean) * rstd * sv.y + bv.y;
    o.z = (v.z - mean) * rstd * sv.z + bv.z;
    o.w = (v.w - mean) * rstd * sv.w + bv.w;
    if (rnd) { o.x = tf32r(o.x); o.y = tf32r(o.y); o.z = tf32r(o.z); o.w = tf32r(o.w); }
    *(float4*)(out + (size_t)row * Cc + c) = o;
}

// ---------------------------------------------------------------------------
// Attention: block per (b, h, 8-query tile). 8 warps, 1 query/warp.
// K transposed in smem (pad 33); q & p via smem; split accumulators for ILP.
// Output tf32-rounded (feeds proj GEMM).
// ---------------------------------------------------------------------------
__global__ void __launch_bounds__(256, 4)
attn_kernel(const float* __restrict__ qkv,
            const int* __restrict__ seq_ls,
            float* __restrict__ y)
{
    const int QTILE = 8;
    int warp = threadIdx.x >> 5;
    int lane = threadIdx.x & 31;
    int qb = blockIdx.x % (Tt / QTILE);
    int h  = (blockIdx.x / (Tt / QTILE)) % Hh;
    int b  = blockIdx.x / ((Tt / QTILE) * Hh);
    int t  = qb * QTILE + warp;

    __shared__ float Kst[Dd][33];
    __shared__ float Vs[32][Dd];
    __shared__ float qs[QTILE][Dd];
    __shared__ float ps[QTILE][32];

    int lv = seq_ls[b];

    const float* qrow = qkv + ((size_t)(b * Tt + t)) * (3 * Cc) + h * Dd;
    qs[warp][lane]      = qrow[lane];
    qs[warp][lane + 32] = qrow[lane + 32];
    __syncwarp();

    const float* kbase = qkv + (size_t)b * Tt * 3 * Cc + Cc + h * Dd;
    const float* vbase = kbase + Cc;

    float mmax = -INFINITY, lsum = 0.f;
    float2 acc = make_float2(0.f, 0.f);

    for (int j0 = 0; j0 < lv; j0 += 32) {
        __syncthreads();
        {
            int key = threadIdx.x >> 3;
            int d0  = (threadIdx.x & 7) * 8;
            int j = j0 + key;
            float4 k0v, k1v, v0v, v1v;
            if (j < lv) {
                const float* kr = kbase + (size_t)j * (3 * Cc);
                k0v = *(const float4*)(kr + d0);
                k1v = *(const float4*)(kr + d0 + 4);
                const float* vr = vbase + (size_t)j * (3 * Cc);
                v0v = *(const float4*)(vr + d0);
                v1v = *(const float4*)(vr + d0 + 4);
            } else {
                k0v = k1v = v0v = v1v = make_float4(0.f, 0.f, 0.f, 0.f);
            }
            Kst[d0 + 0][key] = k0v.x; Kst[d0 + 1][key] = k0v.y;
            Kst[d0 + 2][key] = k0v.z; Kst[d0 + 3][key] = k0v.w;
            Kst[d0 + 4][key] = k1v.x; Kst[d0 + 5][key] = k1v.y;
            Kst[d0 + 6][key] = k1v.z; Kst[d0 + 7][key] = k1v.w;
            *(float4*)&Vs[key][d0]     = v0v;
            *(float4*)&Vs[key][d0 + 4] = v1v;
        }
        __syncthreads();

        // score: 4 independent partial sums (break FMA chain)
        float s0 = 0.f, s1 = 0.f, s2 = 0.f, s3 = 0.f;
        #pragma unroll
        for (int d = 0; d < Dd; d += 4) {
            s0 = fmaf(qs[warp][d + 0], Kst[d + 0][lane], s0);
            s1 = fmaf(qs[warp][d + 1], Kst[d + 1][lane], s1);
            s2 = fmaf(qs[warp][d + 2], Kst[d + 2][lane], s2);
            s3 = fmaf(qs[warp][d + 3], Kst[d + 3][lane], s3);
        }
        float s = ((s0 + s1) + (s2 + s3)) * 0.125f;
        if (j0 + lane >= lv) s = -INFINITY;

        // online softmax update
        float smax = s;
        #pragma unroll
        for (int off = 16; off > 0; off >>= 1)
            smax = fmaxf(smax, __shfl_xor_sync(0xffffffffu, smax, off));
        float mnew = fmaxf(mmax, smax);
        float corr = __expf(mmax - mnew);
        float p = __expf(s - mnew);
        float psum = p;
        #pragma unroll
        for (int off = 16; off > 0; off >>= 1)
            psum += __shfl_xor_sync(0xffffffffu, psum, off);
        lsum = lsum * corr + psum;

        ps[warp][lane] = p;
        __syncwarp();

        // PV: two independent accumulator pairs
        float2 ae = make_float2(0.f, 0.f), ao = make_float2(0.f, 0.f);
        #pragma unroll
        for (int src = 0; src < 32; src += 2) {
            float p0 = ps[warp][src];
            float p1 = ps[warp][src + 1];
            float2 v0 = *(const float2*)&Vs[src][2 * lane];
            float2 v1 = *(const float2*)&Vs[src + 1][2 * lane];
            ae.x = fmaf(p0, v0.x, ae.x); ae.y = fmaf(p0, v0.y, ae.y);
            ao.x = fmaf(p1, v1.x, ao.x); ao.y = fmaf(p1, v1.y, ao.y);
        }
        acc.x = fmaf(acc.x, corr, ae.x + ao.x);
        acc.y = fmaf(acc.y, corr, ae.y + ao.y);
        mmax = mnew;
    }

    float inv = 1.0f / lsum;
    float* yrow = y + ((size_t)(b * Tt + t)) * Cc + h * Dd;
    *(float2*)(yrow + 2 * lane) =
        make_float2(tf32r(acc.x * inv), tf32r(acc.y * inv));
}

// ---------------------------------------------------------------------------
// Head: logits[m, v] = sum_k xf[m,k]*hw[k,v]; V=3.
// ---------------------------------------------------------------------------
__global__ void head_kernel(const float* __restrict__ xf,
                            const float* __restrict__ hw,
                            float* __restrict__ out)
{
    int row = blockIdx.x;
    int tid = threadIdx.x;
    float a0 = 0.f, a1 = 0.f, a2 = 0.f;
    const float* xr = xf + (size_t)row * Cc;
    for (int k = tid; k < Cc; k += 128) {
        float xv = xr[k];
        a0 = fmaf(xv, hw[k * 3 + 0], a0);
        a1 = fmaf(xv, hw[k * 3 + 1], a1);
        a2 = fmaf(xv, hw[k * 3 + 2], a2);
    }
    __shared__ float r0[128], r1[128], r2[128];
    r0[tid] = a0; r1[tid] = a1; r2[tid] = a2;
    __syncthreads();
    for (int off = 64; off > 0; off >>= 1) {
        if (tid < off) { r0[tid] += r0[tid+off]; r1[tid] += r1[tid+off]; r2[tid] += r2[tid+off]; }
        __syncthreads();
    }
    if (tid == 0) {
        out[row * 3 + 0] = r0[0];
        out[row * 3 + 1] = r1[0];
        out[row * 3 + 2] = r2[0];
    }
}

// ---------------------------------------------------------------------------
// Launch
// ---------------------------------------------------------------------------
extern "C" void kernel_launch(void* const* d_in, const int* in_sizes, int n_in,
                              void* d_out, int out_size)
{
    const float* seqs    = (const float*)d_in[0];
    const int*   seq_ls  = (const int*)  d_in[1];
    const float* wte_w   = (const float*)d_in[2];
    const float* wte_b   = (const float*)d_in[3];
    const float* wpe     = (const float*)d_in[4];
    const float* ln1_s   = (const float*)d_in[5];
    const float* ln1_b   = (const float*)d_in[6];
    const float* attn_w  = (const float*)d_in[7];
    const float* attn_b  = (const float*)d_in[8];
    const float* attnp_w = (const float*)d_in[9];
    const float* attnp_b = (const float*)d_in[10];
    const float* ln2_s   = (const float*)d_in[11];
    const float* ln2_b   = (const float*)d_in[12];
    const float* fc_w    = (const float*)d_in[13];
    const float* fc_b    = (const float*)d_in[14];
    const float* proj_w  = (const float*)d_in[15];
    const float* proj_b  = (const float*)d_in[16];
    const float* lnf_s   = (const float*)d_in[17];
    const float* lnf_b   = (const float*)d_in[18];
    const float* head_w  = (const float*)d_in[19];
    float* out = (float*)d_out;

    float *x, *h, *qkv, *y, *fc;
    float *wR_attn, *wR_attnp, *wR_fc, *wR_proj;
    cudaGetSymbolAddress((void**)&x,   g_x);
    cudaGetSymbolAddress((void**)&h,   g_h);
    cudaGetSymbolAddress((void**)&qkv, g_qkv);
    cudaGetSymbolAddress((void**)&y,   g_y);
    cudaGetSymbolAddress((void**)&fc,  g_fc);
    cudaGetSymbolAddress((void**)&wR_attn,  g_wR_attn);
    cudaGetSymbolAddress((void**)&wR_attnp, g_wR_attnp);
    cudaGetSymbolAddress((void**)&wR_fc,    g_wR_fc);
    cudaGetSymbolAddress((void**)&wR_proj,  g_wR_proj);

    cudaFuncSetAttribute(gemm_tc<false, false, false>,
                         cudaFuncAttributeMaxDynamicSharedMemorySize, GEMM_SMEM);
    cudaFuncSetAttribute(gemm_tc<false, true, false>,
                         cudaFuncAttributeMaxDynamicSharedMemorySize, GEMM_SMEM);
    cudaFuncSetAttribute(gemm_tc<true, false, true>,
                         cudaFuncAttributeMaxDynamicSharedMemorySize, GEMM_SMEM);

    // One-time tf32 rounding of all weights (same layout, no transpose)
    round_w<<<2048, 256>>>(attn_w,  wR_attn,  (size_t)Ll * Cc * 3 * Cc / 4);
    round_w<<<1024, 256>>>(attnp_w, wR_attnp, (size_t)Ll * Cc * Cc / 4);
    round_w<<<2048, 256>>>(fc_w,    wR_fc,    (size_t)Ll * Cc * 4 * Cc / 4);
    round_w<<<2048, 256>>>(proj_w,  wR_proj,  (size_t)Ll * 4 * Cc * Cc / 4);

    // Embedding
    embed_kernel<<<Mrows, 256>>>(seqs, wte_w, wte_b, wpe, x);

    for (int l = 0; l < Ll; l++) {
        // LN1 (tf32-rounded output -> GEMM A)
        ln_kernel<<<Mrows, 256>>>(x, ln1_s + l * Cc, ln1_b + l * Cc, h, 1);
        // QKV: [2048,1024] @ [1024,3072]
        gemm_tc<false, false, false><<<dim3(3*Cc/128, Mrows/128), 256, GEMM_SMEM>>>(
            h, wR_attn + (size_t)l * Cc * 3*Cc, attn_b + (size_t)l * 3*Cc,
            nullptr, qkv, 3*Cc, Cc);
        // Attention
        attn_kernel<<<Bb * Hh * (Tt / 8), 256>>>(qkv, seq_ls, y);
        // Attn out-proj + residual
        gemm_tc<false, true, false><<<dim3(Cc/128, Mrows/128), 256, GEMM_SMEM>>>(
            y, wR_attnp + (size_t)l * Cc * Cc, attnp_b + (size_t)l * Cc,
            x, x, Cc, Cc);
        // LN2
        ln_kernel<<<Mrows, 256>>>(x, ln2_s + l * Cc, ln2_b + l * Cc, h, 1);
        // FC + ReLU (tf32-rounded output -> proj2 A)
        gemm_tc<true, false, true><<<dim3(4*Cc/128, Mrows/128), 256, GEMM_SMEM>>>(
            h, wR_fc + (size_t)l * Cc * 4*Cc, fc_b + (size_t)l * 4*Cc,
            nullptr, fc, 4*Cc, Cc);
        // MLP proj + residual: [2048,4096] @ [4096,1024]
        gemm_tc<false, true, false><<<dim3(Cc/128, Mrows/128), 256, GEMM_SMEM>>>(
            fc, wR_proj + (size_t)l * 4*Cc * Cc, proj_b + (size_t)l * Cc,
            x, x, Cc, 4*Cc);
    }

    // Final LN (full fp32) + head
    ln_kernel<<<Mrows, 256>>>(x, lnf_s, lnf_b, h, 0);
    head_kernel<<<Mrows, 128>>>(h, head_w, out);
}

// round 7
// speedup vs baseline: 6.8672x; 1.5869x over previous
#include <cuda_runtime.h>
#include <cuda_bf16.h>
#include <math.h>
#include <stdint.h>

// Problem constants
#define Bb 4
#define Tt 512
#define Cc 1024
#define Hh 16
#define Ll 8
#define FSs 64
#define Vv 3
#define Dd 64          // head dim
#define Mrows (Bb*Tt)  // 2048

// ---------------------------------------------------------------------------
// Device-global scratch (no allocations allowed)
// ---------------------------------------------------------------------------
__device__ float g_x  [Mrows * Cc];
__device__ float g_h  [Mrows * Cc];
__device__ float g_qkv[Mrows * 3 * Cc];
__device__ float g_y  [Mrows * Cc];
__device__ float g_fc [Mrows * 4 * Cc];
__device__ float g_wR_attn [Ll * Cc * 3 * Cc];
__device__ float g_wR_attnp[Ll * Cc * Cc];
__device__ float g_wR_fc   [Ll * Cc * 4 * Cc];
__device__ float g_wR_proj [Ll * 4 * Cc * Cc];

// ---------------------------------------------------------------------------
// Helpers
// ---------------------------------------------------------------------------
__device__ __forceinline__ unsigned f2tf32(float x) {
    unsigned r;
    asm("cvt.rna.tf32.f32 %0, %1;" : "=r"(r) : "f"(x));
    return r;
}
__device__ __forceinline__ float tf32r(float x) { return __uint_as_float(f2tf32(x)); }

__device__ __forceinline__ uint32_t smem_u32(const void* p) {
    uint32_t a;
    asm("{ .reg .u64 t; cvta.to.shared.u64 t, %1; cvt.u32.u64 %0, t; }" : "=r"(a) : "l"(p));
    return a;
}
__device__ __forceinline__ void cp_async16(uint32_t dst, const void* src) {
    asm volatile("cp.async.cg.shared.global [%0], [%1], 16;" :: "r"(dst), "l"(src));
}
#define CP_COMMIT() asm volatile("cp.async.commit_group;" ::: "memory")
#define CP_WAIT(n)  asm volatile("cp.async.wait_group %0;" :: "n"(n) : "memory")

__device__ __forceinline__ void mma_tf32(float c[4], const unsigned a[4],
                                         unsigned b0, unsigned b1) {
    asm volatile(
        "mma.sync.aligned.m16n8k8.row.col.f32.tf32.tf32.f32 "
        "{%0,%1,%2,%3}, {%4,%5,%6,%7}, {%8,%9}, {%0,%1,%2,%3};"
        : "+f"(c[0]), "+f"(c[1]), "+f"(c[2]), "+f"(c[3])
        : "r"(a[0]), "r"(a[1]), "r"(a[2]), "r"(a[3]), "r"(b0), "r"(b1));
}

// ---------------------------------------------------------------------------
// Elementwise tf32 rounding of weights
// ---------------------------------------------------------------------------
__global__ void round_w(const float* __restrict__ in, float* __restrict__ out,
                        size_t n4)
{
    size_t stride = (size_t)gridDim.x * blockDim.x;
    for (size_t i = blockIdx.x * (size_t)blockDim.x + threadIdx.x; i < n4; i += stride) {
        float4 v = ((const float4*)in)[i];
        v.x = tf32r(v.x); v.y = tf32r(v.y); v.z = tf32r(v.z); v.w = tf32r(v.w);
        ((float4*)out)[i] = v;
    }
}

// ---------------------------------------------------------------------------
// TF32 tensor-core GEMM (mma.sync), cp.async 3-stage pipeline, BK=32.
// ---------------------------------------------------------------------------
#define LDA 36
#define LDB 132
#define A_STG (128 * LDA)
#define B_STG (32 * LDB)
#define GEMM_SMEM ((3 * (A_STG + B_STG)) * 4)

template <bool RELU, bool RES, bool ROUND>
__global__ void __launch_bounds__(256, 2)
gemm_tc(const float* __restrict__ A, const float* __restrict__ Bw,
        const float* __restrict__ bias, const float* __restrict__ res,
        float* __restrict__ C, int N, int K)
{
    extern __shared__ float sm[];
    float* Asm = sm;
    float* Bsm = sm + 3 * A_STG;

    int tid = threadIdx.x;
    int lane = tid & 31;
    int warp = tid >> 5;
    int blockRow = blockIdx.y * 128;
    int blockCol = blockIdx.x * 128;

    const float* Abase = A  + (size_t)blockRow * K;
    const float* Bbase = Bw + blockCol;
    int nk = K / 32;

    auto load_stage = [&](int kt, int s) {
        float* as = Asm + s * A_STG;
        float* bs = Bsm + s * B_STG;
        #pragma unroll
        for (int i = 0; i < 4; i++) {
            int q = tid + i * 256;
            int r = q >> 3, c = q & 7;
            cp_async16(smem_u32(as + r * LDA + c * 4),
                       Abase + (size_t)r * K + kt * 32 + c * 4);
            int k = q >> 5, c2 = q & 31;
            cp_async16(smem_u32(bs + k * LDB + c2 * 4),
                       Bbase + (size_t)(kt * 32 + k) * N + c2 * 4);
        }
        CP_COMMIT();
    };

    load_stage(0, 0);
    load_stage(1, 1);

    int m0 = (warp >> 1) * 32;
    int n0 = (warp & 1) * 64;
    int g  = lane >> 2;
    int tg = lane & 3;

    float acc[2][8][4];
    #pragma unroll
    for (int mt = 0; mt < 2; mt++)
        #pragma unroll
        for (int nt = 0; nt < 8; nt++)
            #pragma unroll
            for (int i = 0; i < 4; i++) acc[mt][nt][i] = 0.f;

    for (int kt = 0; kt < nk; kt++) {
        CP_WAIT(1);
        __syncthreads();

        const float* as = Asm + (kt % 3) * A_STG;
        const float* bs = Bsm + (kt % 3) * B_STG;

        #pragma unroll
        for (int ks = 0; ks < 32; ks += 8) {
            unsigned af[2][4];
            #pragma unroll
            for (int mt = 0; mt < 2; mt++) {
                int m = m0 + mt * 16 + g;
                af[mt][0] = __float_as_uint(as[m * LDA + ks + tg]);
                af[mt][1] = __float_as_uint(as[(m + 8) * LDA + ks + tg]);
                af[mt][2] = __float_as_uint(as[m * LDA + ks + tg + 4]);
                af[mt][3] = __float_as_uint(as[(m + 8) * LDA + ks + tg + 4]);
            }
            #pragma unroll
            for (int nt = 0; nt < 8; nt++) {
                int n = n0 + nt * 8 + g;
                unsigned b0 = __float_as_uint(bs[(ks + tg) * LDB + n]);
                unsigned b1 = __float_as_uint(bs[(ks + tg + 4) * LDB + n]);
                mma_tf32(acc[0][nt], af[0], b0, b1);
                mma_tf32(acc[1][nt], af[1], b0, b1);
            }
        }

        if (kt + 2 < nk) load_stage(kt + 2, (kt + 2) % 3);
    }

    #pragma unroll
    for (int mt = 0; mt < 2; mt++) {
        #pragma unroll
        for (int nt = 0; nt < 8; nt++) {
            int col = blockCol + n0 + nt * 8 + tg * 2;
            size_t r0 = blockRow + m0 + mt * 16 + g;
            size_t r1 = r0 + 8;
            float b0v = bias[col], b1v = bias[col + 1];
            float2 o0 = make_float2(acc[mt][nt][0] + b0v, acc[mt][nt][1] + b1v);
            float2 o1 = make_float2(acc[mt][nt][2] + b0v, acc[mt][nt][3] + b1v);
            if (RES) {
                float2 rv0 = *(const float2*)(res + r0 * N + col);
                float2 rv1 = *(const float2*)(res + r1 * N + col);
                o0.x += rv0.x; o0.y += rv0.y;
                o1.x += rv1.x; o1.y += rv1.y;
            }
            if (RELU) {
                o0.x = fmaxf(o0.x, 0.f); o0.y = fmaxf(o0.y, 0.f);
                o1.x = fmaxf(o1.x, 0.f); o1.y = fmaxf(o1.y, 0.f);
            }
            if (ROUND) {
                o0.x = tf32r(o0.x); o0.y = tf32r(o0.y);
                o1.x = tf32r(o1.x); o1.y = tf32r(o1.y);
            }
            *(float2*)(C + r0 * N + col) = o0;
            *(float2*)(C + r1 * N + col) = o1;
        }
    }
}

// ---------------------------------------------------------------------------
// Flash attention (tf32 mma). Block per (64-query tile, h, b); 4 warps;
// each warp owns 16 query rows. K/V tiles (64x64) via cp.async, pipelined.
// S = Q@K^T (Q pre-scaled by 1/8), online softmax, O += P@V.
// smem stride 68 => Q/K/P fragment loads conflict-free.
// ---------------------------------------------------------------------------
#define FLD 68
#define FA_TILE (64 * FLD)
#define FA_SMEM (4 * FA_TILE * 4)

__global__ void __launch_bounds__(128)
attn_fa(const float* __restrict__ qkv,
        const int* __restrict__ seq_ls,
        float* __restrict__ y)
{
    extern __shared__ float fsm[];
    float* Qs = fsm;
    float* Ks = Qs + FA_TILE;
    float* Vs = Ks + FA_TILE;
    float* Ps = Vs + FA_TILE;

    int tid  = threadIdx.x;
    int lane = tid & 31;
    int warp = tid >> 5;
    int g  = lane >> 2;      // 0..7
    int tg = lane & 3;       // 0..3
    int qb = blockIdx.x;     // 0..7
    int h  = blockIdx.y;
    int b  = blockIdx.z;
    int m0w = warp * 16;

    int lv = seq_ls[b];
    int ntiles = (lv + 63) >> 6;

    const float* qkv_b = qkv + (size_t)b * Tt * 3 * Cc;

    // ---- load Q tile (scaled by 1/8, tf32-rounded) ----
    #pragma unroll
    for (int i = 0; i < 8; i++) {
        int q = i * 128 + tid;
        int r = q >> 4, c4 = q & 15;
        float4 v = *(const float4*)(qkv_b + (size_t)(qb * 64 + r) * 3 * Cc + h * Dd + c4 * 4);
        v.x = tf32r(v.x * 0.125f); v.y = tf32r(v.y * 0.125f);
        v.z = tf32r(v.z * 0.125f); v.w = tf32r(v.w * 0.125f);
        *(float4*)(Qs + r * FLD + c4 * 4) = v;
    }

    // cp.async tile loaders (K rows at +Cc, V rows at +2*Cc in qkv)
    uint32_t Ks_u = smem_u32(Ks);
    uint32_t Vs_u = smem_u32(Vs);
    auto load_k = [&](int kt) {
        #pragma unroll
        for (int i = 0; i < 8; i++) {
            int q = i * 128 + tid;
            int r = q >> 4, c4 = q & 15;
            cp_async16(Ks_u + (r * FLD + c4 * 4) * 4,
                       qkv_b + (size_t)(kt * 64 + r) * 3 * Cc + Cc + h * Dd + c4 * 4);
        }
    };
    auto load_v = [&](int kt) {
        #pragma unroll
        for (int i = 0; i < 8; i++) {
            int q = i * 128 + tid;
            int r = q >> 4, c4 = q & 15;
            cp_async16(Vs_u + (r * FLD + c4 * 4) * 4,
                       qkv_b + (size_t)(kt * 64 + r) * 3 * Cc + 2 * Cc + h * Dd + c4 * 4);
        }
    };

    load_k(0); CP_COMMIT();
    load_v(0); CP_COMMIT();

    float m0 = -INFINITY, m1 = -INFINITY;
    float l0 = 0.f, l1 = 0.f;
    float oacc[8][4];
    #pragma unroll
    for (int nt = 0; nt < 8; nt++)
        #pragma unroll
        for (int i = 0; i < 4; i++) oacc[nt][i] = 0.f;

    for (int kt = 0; kt < ntiles; kt++) {
        int j0 = kt * 64;
        CP_WAIT(1);
        __syncthreads();                 // Ks ready (also Qs on first iter)

        // ---- S = Q @ K^T ----
        float s[8][4];
        #pragma unroll
        for (int nt = 0; nt < 8; nt++)
            #pragma unroll
            for (int i = 0; i < 4; i++) s[nt][i] = 0.f;

        #pragma unroll
        for (int ks = 0; ks < 8; ks++) {
            unsigned af[4];
            af[0] = __float_as_uint(Qs[(m0w + g) * FLD + ks * 8 + tg]);
            af[1] = __float_as_uint(Qs[(m0w + g + 8) * FLD + ks * 8 + tg]);
            af[2] = __float_as_uint(Qs[(m0w + g) * FLD + ks * 8 + tg + 4]);
            af[3] = __float_as_uint(Qs[(m0w + g + 8) * FLD + ks * 8 + tg + 4]);
            #pragma unroll
            for (int nt = 0; nt < 8; nt++) {
                unsigned b0 = __float_as_uint(Ks[(nt * 8 + g) * FLD + ks * 8 + tg]);
                unsigned b1 = __float_as_uint(Ks[(nt * 8 + g) * FLD + ks * 8 + tg + 4]);
                mma_tf32(s[nt], af, b0, b1);
            }
        }

        __syncthreads();                 // Ks consumed
        if (kt + 1 < ntiles) load_k(kt + 1);
        CP_COMMIT();

        // ---- mask + online softmax ----
        float mx0 = -INFINITY, mx1 = -INFINITY;
        #pragma unroll
        for (int nt = 0; nt < 8; nt++) {
            int j = j0 + nt * 8 + 2 * tg;
            if (j >= lv)     { s[nt][0] = -INFINITY; s[nt][2] = -INFINITY; }
            if (j + 1 >= lv) { s[nt][1] = -INFINITY; s[nt][3] = -INFINITY; }
            mx0 = fmaxf(mx0, fmaxf(s[nt][0], s[nt][1]));
            mx1 = fmaxf(mx1, fmaxf(s[nt][2], s[nt][3]));
        }
        mx0 = fmaxf(mx0, __shfl_xor_sync(0xffffffffu, mx0, 1));
        mx0 = fmaxf(mx0, __shfl_xor_sync(0xffffffffu, mx0, 2));
        mx1 = fmaxf(mx1, __shfl_xor_sync(0xffffffffu, mx1, 1));
        mx1 = fmaxf(mx1, __shfl_xor_sync(0xffffffffu, mx1, 2));

        float mn0 = fmaxf(m0, mx0), mn1 = fmaxf(m1, mx1);
        float corr0 = __expf(m0 - mn0), corr1 = __expf(m1 - mn1);

        float sum0 = 0.f, sum1 = 0.f;
        #pragma unroll
        for (int nt = 0; nt < 8; nt++) {
            float p00 = __expf(s[nt][0] - mn0);
            float p01 = __expf(s[nt][1] - mn0);
            float p10 = __expf(s[nt][2] - mn1);
            float p11 = __expf(s[nt][3] - mn1);
            sum0 += p00 + p01;
            sum1 += p10 + p11;
            int colr = nt * 8 + 2 * tg;
            *(float2*)(Ps + (m0w + g) * FLD + colr) =
                make_float2(tf32r(p00), tf32r(p01));
            *(float2*)(Ps + (m0w + g + 8) * FLD + colr) =
                make_float2(tf32r(p10), tf32r(p11));
        }
        sum0 += __shfl_xor_sync(0xffffffffu, sum0, 1);
        sum0 += __shfl_xor_sync(0xffffffffu, sum0, 2);
        sum1 += __shfl_xor_sync(0xffffffffu, sum1, 1);
        sum1 += __shfl_xor_sync(0xffffffffu, sum1, 2);
        l0 = l0 * corr0 + sum0;
        l1 = l1 * corr1 + sum1;
        m0 = mn0; m1 = mn1;

        // scale existing O by correction
        #pragma unroll
        for (int nt = 0; nt < 8; nt++) {
            oacc[nt][0] *= corr0; oacc[nt][1] *= corr0;
            oacc[nt][2] *= corr1; oacc[nt][3] *= corr1;
        }

        CP_WAIT(1);
        __syncthreads();                 // Vs ready; Ps visible

        // ---- O += P @ V ----
        #pragma unroll
        for (int ks = 0; ks < 8; ks++) {
            unsigned af[4];
            af[0] = __float_as_uint(Ps[(m0w + g) * FLD + ks * 8 + tg]);
            af[1] = __float_as_uint(Ps[(m0w + g + 8) * FLD + ks * 8 + tg]);
            af[2] = __float_as_uint(Ps[(m0w + g) * FLD + ks * 8 + tg + 4]);
            af[3] = __float_as_uint(Ps[(m0w + g + 8) * FLD + ks * 8 + tg + 4]);
            #pragma unroll
            for (int nt = 0; nt < 8; nt++) {
                unsigned b0 = __float_as_uint(Vs[(ks * 8 + tg) * FLD + nt * 8 + g]);
                unsigned b1 = __float_as_uint(Vs[(ks * 8 + tg + 4) * FLD + nt * 8 + g]);
                mma_tf32(oacc[nt], af, b0, b1);
            }
        }

        __syncthreads();                 // Vs consumed
        if (kt + 1 < ntiles) load_v(kt + 1);
        CP_COMMIT();
    }

    // ---- write O (tf32-rounded; feeds proj GEMM) ----
    float inv0 = 1.0f / l0, inv1 = 1.0f / l1;
    int t0 = qb * 64 + m0w + g;
    #pragma unroll
    for (int nt = 0; nt < 8; nt++) {
        int col = h * Dd + nt * 8 + 2 * tg;
        *(float2*)(y + (size_t)(b * Tt + t0) * Cc + col) =
            make_float2(tf32r(oacc[nt][0] * inv0), tf32r(oacc[nt][1] * inv0));
        *(float2*)(y + (size_t)(b * Tt + t0 + 8) * Cc + col) =
            make_float2(tf32r(oacc[nt][2] * inv1), tf32r(oacc[nt][3] * inv1));
    }
}

// ---------------------------------------------------------------------------
// Embedding
// ---------------------------------------------------------------------------
__global__ void embed_kernel(const float* __restrict__ seqs,
                             const float* __restrict__ wte_w,
                             const float* __restrict__ wte_b,
                             const float* __restrict__ wpe,
                             float* __restrict__ x)
{
    int m = blockIdx.x;
    int t = m % Tt;
    __shared__ float sf[FSs];
    if (threadIdx.x < FSs) sf[threadIdx.x] = seqs[m * FSs + threadIdx.x];
    __syncthreads();

    #pragma unroll
    for (int cc = 0; cc < 4; cc++) {
        int c = threadIdx.x + cc * 256;
        float acc = wte_b[c] + wpe[t * Cc + c];
        #pragma unroll 8
        for (int f = 0; f < FSs; f++)
            acc = fmaf(sf[f], wte_w[f * Cc + c], acc);
        x[m * Cc + c] = acc;
    }
}

// ---------------------------------------------------------------------------
// LayerNorm
// ---------------------------------------------------------------------------
__global__ void ln_kernel(const float* __restrict__ x,
                          const float* __restrict__ s,
                          const float* __restrict__ b,
                          float* __restrict__ out, int rnd)
{
    int row = blockIdx.x;
    int tid = threadIdx.x;
    const float* xr = x + (size_t)row * Cc;

    float4 v = *(const float4*)(xr + tid * 4);
    float sum = v.x + v.y + v.z + v.w;
    float sumsq = v.x*v.x + v.y*v.y + v.z*v.z + v.w*v.w;

    #pragma unroll
    for (int off = 16; off > 0; off >>= 1) {
        sum   += __shfl_xor_sync(0xffffffffu, sum, off);
        sumsq += __shfl_xor_sync(0xffffffffu, sumsq, off);
    }
    __shared__ float red1[8], red2[8];
    int wid = tid >> 5, lane = tid & 31;
    if (lane == 0) { red1[wid] = sum; red2[wid] = sumsq; }
    __syncthreads();
    if (wid == 0) {
        float s1 = red1[lane & 7], s2 = red2[lane & 7];
        #pragma unroll
        for (int off = 4; off > 0; off >>= 1) {
            s1 += __shfl_xor_sync(0xffffffffu, s1, off);
            s2 += __shfl_xor_sync(0xffffffffu, s2, off);
        }
        if (lane == 0) { red1[0] = s1; red2[0] = s2; }
    }
    __syncthreads();
    float mean = red1[0] * (1.0f / Cc);
    float var  = red2[0] * (1.0f / Cc) - mean * mean;
    float rstd = rsqrtf(var + 1e-5f);

    int c = tid * 4;
    float4 sv = *(const float4*)(s + c);
    float4 bv = *(const float4*)(b + c);
    float4 o;
    o.x = (v.x - mean) * rstd * sv.x + bv.x;
    o.y = (v.y - mean) * rstd * sv.y + bv.y;
    o.z = (v.z - mean) * rstd * sv.z + bv.z;
    o.w = (v.w - mean) * rstd * sv.w + bv.w;
    if (rnd) { o.x = tf32r(o.x); o.y = tf32r(o.y); o.z = tf32r(o.z); o.w = tf32r(o.w); }
    *(float4*)(out + (size_t)row * Cc + c) = o;
}

// ---------------------------------------------------------------------------
// Head
// ---------------------------------------------------------------------------
__global__ void head_kernel(const float* __restrict__ xf,
                            const float* __restrict__ hw,
                            float* __restrict__ out)
{
    int row = blockIdx.x;
    int tid = threadIdx.x;
    float a0 = 0.f, a1 = 0.f, a2 = 0.f;
    const float* xr = xf + (size_t)row * Cc;
    for (int k = tid; k < Cc; k += 128) {
        float xv = xr[k];
        a0 = fmaf(xv, hw[k * 3 + 0], a0);
        a1 = fmaf(xv, hw[k * 3 + 1], a1);
        a2 = fmaf(xv, hw[k * 3 + 2], a2);
    }
    __shared__ float r0[128], r1[128], r2[128];
    r0[tid] = a0; r1[tid] = a1; r2[tid] = a2;
    __syncthreads();
    for (int off = 64; off > 0; off >>= 1) {
        if (tid < off) { r0[tid] += r0[tid+off]; r1[tid] += r1[tid+off]; r2[tid] += r2[tid+off]; }
        __syncthreads();
    }
    if (tid == 0) {
        out[row * 3 + 0] = r0[0];
        out[row * 3 + 1] = r1[0];
        out[row * 3 + 2] = r2[0];
    }
}

// ---------------------------------------------------------------------------
// Launch
// ---------------------------------------------------------------------------
extern "C" void kernel_launch(void* const* d_in, const int* in_sizes, int n_in,
                              void* d_out, int out_size)
{
    const float* seqs    = (const float*)d_in[0];
    const int*   seq_ls  = (const int*)  d_in[1];
    const float* wte_w   = (const float*)d_in[2];
    const float* wte_b   = (const float*)d_in[3];
    const float* wpe     = (const float*)d_in[4];
    const float* ln1_s   = (const float*)d_in[5];
    const float* ln1_b   = (const float*)d_in[6];
    const float* attn_w  = (const float*)d_in[7];
    const float* attn_b  = (const float*)d_in[8];
    const float* attnp_w = (const float*)d_in[9];
    const float* attnp_b = (const float*)d_in[10];
    const float* ln2_s   = (const float*)d_in[11];
    const float* ln2_b   = (const float*)d_in[12];
    const float* fc_w    = (const float*)d_in[13];
    const float* fc_b    = (const float*)d_in[14];
    const float* proj_w  = (const float*)d_in[15];
    const float* proj_b  = (const float*)d_in[16];
    const float* lnf_s   = (const float*)d_in[17];
    const float* lnf_b   = (const float*)d_in[18];
    const float* head_w  = (const float*)d_in[19];
    float* out = (float*)d_out;

    float *x, *h, *qkv, *y, *fc;
    float *wR_attn, *wR_attnp, *wR_fc, *wR_proj;
    cudaGetSymbolAddress((void**)&x,   g_x);
    cudaGetSymbolAddress((void**)&h,   g_h);
    cudaGetSymbolAddress((void**)&qkv, g_qkv);
    cudaGetSymbolAddress((void**)&y,   g_y);
    cudaGetSymbolAddress((void**)&fc,  g_fc);
    cudaGetSymbolAddress((void**)&wR_attn,  g_wR_attn);
    cudaGetSymbolAddress((void**)&wR_attnp, g_wR_attnp);
    cudaGetSymbolAddress((void**)&wR_fc,    g_wR_fc);
    cudaGetSymbolAddress((void**)&wR_proj,  g_wR_proj);

    cudaFuncSetAttribute(gemm_tc<false, false, false>,
                         cudaFuncAttributeMaxDynamicSharedMemorySize, GEMM_SMEM);
    cudaFuncSetAttribute(gemm_tc<false, true, false>,
                         cudaFuncAttributeMaxDynamicSharedMemorySize, GEMM_SMEM);
    cudaFuncSetAttribute(gemm_tc<true, false, true>,
                         cudaFuncAttributeMaxDynamicSharedMemorySize, GEMM_SMEM);
    cudaFuncSetAttribute(attn_fa,
                         cudaFuncAttributeMaxDynamicSharedMemorySize, FA_SMEM);

    // One-time tf32 rounding of all weights
    round_w<<<2048, 256>>>(attn_w,  wR_attn,  (size_t)Ll * Cc * 3 * Cc / 4);
    round_w<<<1024, 256>>>(attnp_w, wR_attnp, (size_t)Ll * Cc * Cc / 4);
    round_w<<<2048, 256>>>(fc_w,    wR_fc,    (size_t)Ll * Cc * 4 * Cc / 4);
    round_w<<<2048, 256>>>(proj_w,  wR_proj,  (size_t)Ll * 4 * Cc * Cc / 4);

    // Embedding
    embed_kernel<<<Mrows, 256>>>(seqs, wte_w, wte_b, wpe, x);

    for (int l = 0; l < Ll; l++) {
        ln_kernel<<<Mrows, 256>>>(x, ln1_s + l * Cc, ln1_b + l * Cc, h, 1);
        gemm_tc<false, false, false><<<dim3(3*Cc/128, Mrows/128), 256, GEMM_SMEM>>>(
            h, wR_attn + (size_t)l * Cc * 3*Cc, attn_b + (size_t)l * 3*Cc,
            nullptr, qkv, 3*Cc, Cc);
        attn_fa<<<dim3(Tt/64, Hh, Bb), 128, FA_SMEM>>>(qkv, seq_ls, y);
        gemm_tc<false, true, false><<<dim3(Cc/128, Mrows/128), 256, GEMM_SMEM>>>(
            y, wR_attnp + (size_t)l * Cc * Cc, attnp_b + (size_t)l * Cc,
            x, x, Cc, Cc);
        ln_kernel<<<Mrows, 256>>>(x, ln2_s + l * Cc, ln2_b + l * Cc, h, 1);
        gemm_tc<true, false, true><<<dim3(4*Cc/128, Mrows/128), 256, GEMM_SMEM>>>(
            h, wR_fc + (size_t)l * Cc * 4*Cc, fc_b + (size_t)l * 4*Cc,
            nullptr, fc, 4*Cc, Cc);
        gemm_tc<false, true, false><<<dim3(Cc/128, Mrows/128), 256, GEMM_SMEM>>>(
            fc, wR_proj + (size_t)l * 4*Cc * Cc, proj_b + (size_t)l * Cc,
            x, x, Cc, 4*Cc);
    }

    ln_kernel<<<Mrows, 256>>>(x, lnf_s, lnf_b, h, 0);
    head_kernel<<<Mrows, 128>>>(h, head_w, out);
}